// round 13
// baseline (speedup 1.0000x reference)
#include <cuda_runtime.h>
#include <cuda_bf16.h>
#include <math.h>

// ---------------- problem constants ----------------
#define T_TOK 8192
#define DMODEL 1024
#define FFDIM 4096
#define NEXP 8
#define CAP 2560
#define SEQ 2048
#define NBATCH 4
#define LSCALE 2.0f

// ---------------- device scratch ----------------
__device__ float g_w2wh[FFDIM * 2];
__device__ float g_b2wh[NEXP * 2 * 2];
__device__ int   g_exp[2][T_TOK];
__device__ float g_gate[2][T_TOK];
__device__ float g_u1[2][T_TOK][2];
__device__ float g_acc[T_TOK][2][4];
__device__ int   g_cnt[NEXP];                  // zeroed by route_kernel each launch
__device__ float g_part[NBATCH][8][2];

__device__ __nv_bfloat16 g_xhi[T_TOK * DMODEL];
__device__ __nv_bfloat16 g_xlo[T_TOK * DMODEL];
__device__ __nv_bfloat16 g_w1t_hi[FFDIM * DMODEL];
__device__ __nv_bfloat16 g_w1t_lo[FFDIM * DMODEL];

// ---------------- PTX helpers ----------------
__device__ __forceinline__ unsigned smem_u32(const void* p) {
    unsigned a;
    asm("{ .reg .u64 t; cvta.to.shared.u64 t, %1; cvt.u32.u64 %0, t; }" : "=r"(a) : "l"(p));
    return a;
}
#define CP_ASYNC16(saddr, gptr) \
    asm volatile("cp.async.cg.shared.global [%0], [%1], 16;" :: "r"(saddr), "l"(gptr))
#define CP_COMMIT() asm volatile("cp.async.commit_group;" ::: "memory")
#define CP_WAIT1()  asm volatile("cp.async.wait_group 1;" ::: "memory")
#define CP_WAIT0()  asm volatile("cp.async.wait_group 0;" ::: "memory")

__device__ __forceinline__ void ldmx4(unsigned addr, unsigned& r0, unsigned& r1,
                                      unsigned& r2, unsigned& r3) {
    asm volatile("ldmatrix.sync.aligned.m8n8.x4.shared.b16 {%0,%1,%2,%3}, [%4];"
                 : "=r"(r0), "=r"(r1), "=r"(r2), "=r"(r3) : "r"(addr));
}
__device__ __forceinline__ void mma16816(float* c, const unsigned* a, const unsigned* b) {
    asm volatile("mma.sync.aligned.m16n8k16.row.col.f32.bf16.bf16.f32 "
                 "{%0,%1,%2,%3}, {%4,%5,%6,%7}, {%8,%9}, {%0,%1,%2,%3};"
                 : "+f"(c[0]), "+f"(c[1]), "+f"(c[2]), "+f"(c[3])
                 : "r"(a[0]), "r"(a[1]), "r"(a[2]), "r"(a[3]), "r"(b[0]), "r"(b[1]));
}

// ---------------- merged aux kernel: gate | convert_w | prep ----------------
#define GATE_BLOCKS 1024
#define CONVW_BLOCKS 4096
#define PREP_BLOCKS 513

__global__ void aux_kernel(const float* __restrict__ x,  const float* __restrict__ Wg,
                           const float* __restrict__ A1, const float* __restrict__ W1,
                           const float* __restrict__ W2, const float* __restrict__ Wh,
                           const float* __restrict__ B2) {
    __shared__ float sbuf[NEXP * DMODEL];     // 32 KB, reused per role
    int bid = blockIdx.x, tid = threadIdx.x;

    if (bid < GATE_BLOCKS) {
        // ---- gating + u1 + x hi/lo conversion + hist + zero accum, x in registers ----
        float (*wgt)[DMODEL] = (float(*)[DMODEL])sbuf;
        for (int i = tid; i < DMODEL * NEXP; i += 256) {
            int d = i >> 3, e = i & 7;
            wgt[e][d] = Wg[i];
        }
        __syncthreads();

        int warp = tid >> 5, lane = tid & 31;
        int t = bid * 8 + warp;
        const float* xr = x + (size_t)t * DMODEL;

        float4 xv[8];
#pragma unroll
        for (int i = 0; i < 8; i++) xv[i] = *(const float4*)(xr + i * 128 + lane * 4);

#pragma unroll
        for (int i = 0; i < 8; i++) {
            int d = i * 128 + lane * 4;
            __nv_bfloat16 h0 = __float2bfloat16(xv[i].x), h1 = __float2bfloat16(xv[i].y);
            __nv_bfloat16 h2 = __float2bfloat16(xv[i].z), h3 = __float2bfloat16(xv[i].w);
            __nv_bfloat162 hi01 = __halves2bfloat162(h0, h1);
            __nv_bfloat162 hi23 = __halves2bfloat162(h2, h3);
            __nv_bfloat162 lo01 = __floats2bfloat162_rn(xv[i].x - __bfloat162float(h0),
                                                        xv[i].y - __bfloat162float(h1));
            __nv_bfloat162 lo23 = __floats2bfloat162_rn(xv[i].z - __bfloat162float(h2),
                                                        xv[i].w - __bfloat162float(h3));
            uint2 hv, lv;
            hv.x = *(unsigned*)&hi01; hv.y = *(unsigned*)&hi23;
            lv.x = *(unsigned*)&lo01; lv.y = *(unsigned*)&lo23;
            *(uint2*)(g_xhi + (size_t)t * DMODEL + d) = hv;
            *(uint2*)(g_xlo + (size_t)t * DMODEL + d) = lv;
        }

        float lg[8] = {};
#pragma unroll
        for (int e = 0; e < 8; e++) {
#pragma unroll
            for (int i = 0; i < 8; i++) {
                float4 wv = *(const float4*)&wgt[e][i * 128 + lane * 4];
                lg[e] += xv[i].x * wv.x + xv[i].y * wv.y + xv[i].z * wv.z + xv[i].w * wv.w;
            }
        }
#pragma unroll
        for (int e = 0; e < 8; e++)
            for (int o = 16; o; o >>= 1) lg[e] += __shfl_xor_sync(~0u, lg[e], o);

        float v0 = -1e30f, v1 = -1e30f; int e0 = 0, e1 = 0;
#pragma unroll
        for (int e = 0; e < 8; e++) {
            float l = lg[e];
            if (l > v0)      { v1 = v0; e1 = e0; v0 = l; e0 = e; }
            else if (l > v1) { v1 = l;  e1 = e; }
        }
        float q  = expf(v1 - v0);
        float g0 = 1.0f / (1.0f + q);
        float g1 = q * g0;

        float u00 = 0.f, u01 = 0.f, u10 = 0.f, u11 = 0.f;
        const float* a1e0 = A1 + (size_t)e0 * DMODEL * 2;
        const float* a1e1 = A1 + (size_t)e1 * DMODEL * 2;
#pragma unroll
        for (int i = 0; i < 8; i++) {
            int base = 2 * (i * 128 + lane * 4);
            float4 p0 = *(const float4*)(a1e0 + base);
            float4 p1 = *(const float4*)(a1e0 + base + 4);
            u00 += xv[i].x * p0.x + xv[i].y * p0.z + xv[i].z * p1.x + xv[i].w * p1.z;
            u01 += xv[i].x * p0.y + xv[i].y * p0.w + xv[i].z * p1.y + xv[i].w * p1.w;
            float4 q0 = *(const float4*)(a1e1 + base);
            float4 q1 = *(const float4*)(a1e1 + base + 4);
            u10 += xv[i].x * q0.x + xv[i].y * q0.z + xv[i].z * q1.x + xv[i].w * q1.z;
            u11 += xv[i].x * q0.y + xv[i].y * q0.w + xv[i].z * q1.y + xv[i].w * q1.w;
        }
        for (int o = 16; o; o >>= 1) {
            u00 += __shfl_xor_sync(~0u, u00, o); u01 += __shfl_xor_sync(~0u, u01, o);
            u10 += __shfl_xor_sync(~0u, u10, o); u11 += __shfl_xor_sync(~0u, u11, o);
        }
        if (lane == 0) {
            g_exp[0][t] = e0;  g_exp[1][t] = e1;
            g_gate[0][t] = g0; g_gate[1][t] = g1;
            g_u1[0][t][0] = LSCALE * u00; g_u1[0][t][1] = LSCALE * u01;
            g_u1[1][t][0] = LSCALE * u10; g_u1[1][t][1] = LSCALE * u11;
            atomicAdd(&g_cnt[e0], 1);
            atomicAdd(&g_cnt[e1], 1);
        }
        if (lane < 8) (&g_acc[t][0][0])[lane] = 0.f;
    } else if (bid < GATE_BLOCKS + CONVW_BLOCKS) {
        // ---- W1 -> transposed bf16 hi/lo ----
        float (*tile)[33] = (float(*)[33])sbuf;
        int idx = bid - GATE_BLOCKS;
        int bx = idx & 127, by = idx >> 7;
        int tx = tid & 31, ty = tid >> 5;
#pragma unroll
        for (int i = 0; i < 4; i++) {
            int k = by * 32 + ty + i * 8, n = bx * 32 + tx;
            tile[ty + i * 8][tx] = W1[(size_t)k * FFDIM + n];
        }
        __syncthreads();
#pragma unroll
        for (int i = 0; i < 4; i++) {
            int n = bx * 32 + ty + i * 8, k = by * 32 + tx;
            float v = tile[tx][ty + i * 8];
            __nv_bfloat16 h = __float2bfloat16(v);
            g_w1t_hi[(size_t)n * DMODEL + k] = h;
            g_w1t_lo[(size_t)n * DMODEL + k] = __float2bfloat16(v - __bfloat162float(h));
        }
    } else {
        // ---- prep: head-folded matrices (doesn't touch g_cnt) ----
        int pb = bid - GATE_BLOCKS - CONVW_BLOCKS;
        int gw = pb * 8 + (tid >> 5);
        int lane = tid & 31;
        if (gw < FFDIM) {
            const float* wr = W2 + (size_t)gw * DMODEL;
            float s0 = 0.f, s1 = 0.f;
            for (int d = lane; d < DMODEL; d += 32) {
                float wv = wr[d];
                s0 += wv * Wh[2 * d]; s1 += wv * Wh[2 * d + 1];
            }
            for (int o = 16; o; o >>= 1) {
                s0 += __shfl_xor_sync(~0u, s0, o); s1 += __shfl_xor_sync(~0u, s1, o);
            }
            if (lane == 0) { g_w2wh[2 * gw] = s0; g_w2wh[2 * gw + 1] = s1; }
        } else {
            int w = gw - FFDIM;
            for (int p = 2 * w; p < 2 * w + 2 && p < 16; p++) {
                const float* br = B2 + (size_t)p * DMODEL;
                float s0 = 0.f, s1 = 0.f;
                for (int d = lane; d < DMODEL; d += 32) {
                    float bv = br[d];
                    s0 += bv * Wh[2 * d]; s1 += bv * Wh[2 * d + 1];
                }
                for (int o = 16; o; o >>= 1) {
                    s0 += __shfl_xor_sync(~0u, s0, o); s1 += __shfl_xor_sync(~0u, s1, o);
                }
                if (lane == 0) { g_b2wh[2 * p] = s0; g_b2wh[2 * p + 1] = s1; }
            }
        }
    }
}

// ---------------- kernel: capacity scan (fast path) + g_cnt reset ----------------
__global__ void route_kernel() {
    int tid = threadIdx.x;
    bool over = false;
#pragma unroll
    for (int e = 0; e < 8; e++) over |= (g_cnt[e] > CAP);
    __syncthreads();
    if (tid < 8) g_cnt[tid] = 0;
    if (!over) return;

    int lane = tid & 31, warp = tid >> 5;
    int base = tid * 16;

    unsigned char le[16];
    int cnt[8] = {};
    for (int j = 0; j < 16; j++) {
        int a = base + j;
        int s = a >> 13, t = a & (T_TOK - 1);
        int e = g_exp[s][t];
        le[j] = (unsigned char)e;
        cnt[e]++;
    }
    __shared__ int warpsum[32][8];
    int excl[8];
#pragma unroll
    for (int e = 0; e < 8; e++) {
        int v = cnt[e], inc = v;
        for (int o = 1; o < 32; o <<= 1) {
            int nv = __shfl_up_sync(~0u, inc, o);
            if (lane >= o) inc += nv;
        }
        excl[e] = inc - v;
        if (lane == 31) warpsum[warp][e] = inc;
    }
    __syncthreads();
    if (warp == 0) {
#pragma unroll
        for (int e = 0; e < 8; e++) {
            int v = warpsum[lane][e], inc = v;
            for (int o = 1; o < 32; o <<= 1) {
                int nv = __shfl_up_sync(~0u, inc, o);
                if (lane >= o) inc += nv;
            }
            warpsum[lane][e] = inc - v;
        }
    }
    __syncthreads();
#pragma unroll
    for (int e = 0; e < 8; e++) excl[e] += warpsum[warp][e];

    for (int j = 0; j < 16; j++) {
        int a = base + j;
        int s = a >> 13, t = a & (T_TOK - 1);
        int e = le[j];
        int pos = excl[e]++;
        if (pos >= CAP) g_gate[s][t] = 0.f;
    }
}

// ---------------- HMMA GEMM, term-inner (128x256 CTA, 4x4 warps of 32x64) -------
#define GBM 128
#define GBN 256
#define GKC 64
#define NCHUNK 16
#define A_BYTES 32768
#define B_BYTES 65536
#define STAGE_BYTES (A_BYTES + B_BYTES)
#define NSTAGE 2
#define SMEM_REQ (NSTAGE * STAGE_BYTES)   // 192 KB, 1 CTA/SM, 16 warps
#define NTHR 512

__device__ __forceinline__ void issue_stage(unsigned sbase, int chunk, int mBase, int nBase,
                                            int tid) {
    int k0 = chunk * GKC;
#pragma unroll
    for (int q = 0; q < 4; q++) {
        int u = q * NTHR + tid;
        int row = u >> 3, ch = u & 7;
        const __nv_bfloat16* ap = (q < 2) ? (g_xhi + (size_t)(mBase + row) * DMODEL)
                                          : (g_xlo + (size_t)(mBase + row - 128) * DMODEL);
        unsigned off = row * 128 + (((unsigned)(ch ^ (row & 7))) << 4);
        CP_ASYNC16(sbase + off, ap + k0 + ch * 8);
    }
#pragma unroll
    for (int q = 0; q < 8; q++) {
        int u = q * NTHR + tid;
        int row = u >> 3, ch = u & 7;
        const __nv_bfloat16* bp = (q < 4) ? (g_w1t_hi + (size_t)(nBase + row) * DMODEL)
                                          : (g_w1t_lo + (size_t)(nBase + row - 256) * DMODEL);
        unsigned off = A_BYTES + row * 128 + (((unsigned)(ch ^ (row & 7))) << 4);
        CP_ASYNC16(sbase + off, bp + k0 + ch * 8);
    }
}

__global__ __launch_bounds__(NTHR, 1)
void ffn_tc_kernel(const float* __restrict__ B1, const float* __restrict__ A2) {
    extern __shared__ char dsm[];
    unsigned sbase = smem_u32(dsm);

    int tid = threadIdx.x, wid = tid >> 5, lane = tid & 31;
    int wm = wid & 3, wn = wid >> 2;
    int mBase = blockIdx.y * GBM, nBase = blockIdx.x * GBN;

    float acc[2][8][4] = {};

    issue_stage(sbase + 0 * STAGE_BYTES, 0, mBase, nBase, tid); CP_COMMIT();
    issue_stage(sbase + 1 * STAGE_BYTES, 1, mBase, nBase, tid); CP_COMMIT();

    int grp = lane >> 3, r8 = lane & 7;
    int a_m  = wm * 32 + (grp & 1) * 8 + r8;
    int a_ch = grp >> 1;
    int b_n  = wn * 64 + (grp >> 1) * 8 + r8;
    int b_ch = grp & 1;

    for (int c = 0; c < NCHUNK; c++) {
        if (c >= NCHUNK - 1) { CP_WAIT0(); } else { CP_WAIT1(); }
        __syncthreads();
        unsigned st = sbase + (c & 1) * STAGE_BYTES;

        // register double-buffered A fragments: [buf][mf][4]
        unsigned ah[2][2][4], al[2][2][4];
#pragma unroll
        for (int mf = 0; mf < 2; mf++) {              // preload ks=0
            int m = a_m + mf * 16;
            unsigned sw = (((unsigned)(a_ch ^ (m & 7))) << 4);
            ldmx4(st + m * 128 + sw, ah[0][mf][0], ah[0][mf][1], ah[0][mf][2], ah[0][mf][3]);
            ldmx4(st + (m + 128) * 128 + sw, al[0][mf][0], al[0][mf][1], al[0][mf][2], al[0][mf][3]);
        }
#pragma unroll
        for (int ks = 0; ks < 4; ks++) {
            int cur = ks & 1, nxt = cur ^ 1;
            unsigned b[8][2];
#pragma unroll
            for (int nf2 = 0; nf2 < 4; nf2++) {       // W_hi fragments
                int n = b_n + nf2 * 16;
                int ch = 2 * ks + b_ch;
                unsigned addr = st + A_BYTES + n * 128 + (((unsigned)(ch ^ (n & 7))) << 4);
                ldmx4(addr, b[nf2 * 2][0], b[nf2 * 2][1], b[nf2 * 2 + 1][0], b[nf2 * 2 + 1][1]);
            }
#pragma unroll
            for (int mf = 0; mf < 2; mf++)
#pragma unroll
                for (int nf = 0; nf < 8; nf++) {
                    mma16816(acc[mf][nf], ah[cur][mf], b[nf]);   // x_hi . W_hi
                    mma16816(acc[mf][nf], al[cur][mf], b[nf]);   // x_lo . W_hi
                }
            if (ks < 3) {                             // prefetch next ks A fragments
#pragma unroll
                for (int mf = 0; mf < 2; mf++) {
                    int m = a_m + mf * 16;
                    int ch = 2 * (ks + 1) + a_ch;
                    unsigned sw = (((unsigned)(ch ^ (m & 7))) << 4);
                    ldmx4(st + m * 128 + sw,
                          ah[nxt][mf][0], ah[nxt][mf][1], ah[nxt][mf][2], ah[nxt][mf][3]);
                    ldmx4(st + (m + 128) * 128 + sw,
                          al[nxt][mf][0], al[nxt][mf][1], al[nxt][mf][2], al[nxt][mf][3]);
                }
            }
#pragma unroll
            for (int nf2 = 0; nf2 < 4; nf2++) {       // W_lo fragments (reuse b regs)
                int n = b_n + nf2 * 16 + 256;
                int ch = 2 * ks + b_ch;
                unsigned addr = st + A_BYTES + n * 128 + (((unsigned)(ch ^ (n & 7))) << 4);
                ldmx4(addr, b[nf2 * 2][0], b[nf2 * 2][1], b[nf2 * 2 + 1][0], b[nf2 * 2 + 1][1]);
            }
#pragma unroll
            for (int mf = 0; mf < 2; mf++)
#pragma unroll
                for (int nf = 0; nf < 8; nf++)
                    mma16816(acc[mf][nf], ah[cur][mf], b[nf]);   // x_hi . W_lo
        }
        __syncthreads();
        if (c + 2 < NCHUNK) {
            issue_stage(sbase + (c & 1) * STAGE_BYTES, c + 2, mBase, nBase, tid);
            CP_COMMIT();
        }
    }

    // ---- epilogue ----
    float* ep_w  = (float*)dsm;                       // [256][33]
    float* ep_w2 = (float*)(dsm + 33792);             // [256][2]
    float* ep_g  = (float*)(dsm + 35840);             // [2][128]
    float* ep_u  = (float*)(dsm + 36864);             // [2][128][2]
    int*   ep_e  = (int*)  (dsm + 38912);             // [2][128]

#pragma unroll
    for (int it = 0; it < 16; it++) {
        int idx = it * NTHR + tid;
        int n = idx >> 5, e = (idx >> 2) & 7, q = idx & 3;
        float v;
        if (q < 2) v = B1[(size_t)(e * 2 + q) * FFDIM + nBase + n];
        else       v = A2[(size_t)e * FFDIM * 2 + (size_t)(nBase + n) * 2 + (q - 2)];
        ep_w[n * 33 + e * 4 + q] = v;
    }
    ep_w2[tid] = g_w2wh[nBase * 2 + tid];
    if (tid < 256) {
        int s = tid >> 7, m = tid & 127;
        int t = mBase + m;
        ep_g[s * 128 + m] = g_gate[s][t];
        ep_e[s * 128 + m] = g_exp[s][t];
        ep_u[(s * 128 + m) * 2 + 0] = g_u1[s][t][0];
        ep_u[(s * 128 + m) * 2 + 1] = g_u1[s][t][1];
    }
    __syncthreads();

    const float GC  = 0.7978845608028654f;
    const float T2L = 2.8853900817779268f;
    int quad = lane >> 2, qi = lane & 3;

#pragma unroll
    for (int mf = 0; mf < 2; mf++) {
#pragma unroll
        for (int q8 = 0; q8 < 2; q8++) {
            int m = wm * 32 + mf * 16 + q8 * 8 + quad;
            int t = mBase + m;
#pragma unroll
            for (int s = 0; s < 2; s++) {
                float w = ep_g[s * 128 + m];
                float p0 = 0.f, p1 = 0.f, p2 = 0.f, p3 = 0.f;
                if (w != 0.f) {
                    int e = ep_e[s * 128 + m];
                    float u0 = ep_u[(s * 128 + m) * 2 + 0];
                    float u1 = ep_u[(s * 128 + m) * 2 + 1];
                    const float* wb = ep_w + e * 4;
#pragma unroll
                    for (int nf = 0; nf < 8; nf++) {
#pragma unroll
                        for (int r = 0; r < 2; r++) {
                            int n = wn * 64 + nf * 8 + 2 * qi + r;
                            float av = acc[mf][nf][q8 * 2 + r];
                            float b1r0 = wb[n * 33 + 0], b1r1 = wb[n * 33 + 1];
                            float v = av + u0 * b1r0 + u1 * b1r1;
                            float yy = GC * (v + 0.044715f * v * v * v);
                            float ex = exp2f(yy * T2L);
                            float th = 1.0f - __fdividef(2.0f, ex + 1.0f);
                            float h  = 0.5f * v * (1.0f + th);
                            p0 += h * ep_w2[n * 2];
                            p1 += h * ep_w2[n * 2 + 1];
                            p2 += h * wb[n * 33 + 2];
                            p3 += h * wb[n * 33 + 3];
                        }
                    }
                }
                for (int o = 1; o <= 2; o <<= 1) {
                    p0 += __shfl_xor_sync(~0u, p0, o);
                    p1 += __shfl_xor_sync(~0u, p1, o);
                    p2 += __shfl_xor_sync(~0u, p2, o);
                    p3 += __shfl_xor_sync(~0u, p3, o);
                }
                if (qi == 0 && w != 0.f) {
                    atomicAdd(&g_acc[t][s][0], p0);
                    atomicAdd(&g_acc[t][s][1], p1);
                    atomicAdd(&g_acc[t][s][2], p2);
                    atomicAdd(&g_acc[t][s][3], p3);
                }
            }
        }
    }
}

// ---------------- combine + pool: two-stage deterministic reduction ----------------
__global__ void final_part_kernel() {
    __shared__ float red[256][2];
    int part = blockIdx.x, b = blockIdx.y, tid = threadIdx.x;
    int t = b * SEQ + part * 256 + tid;
    float s0 = 0.f, s1 = 0.f;
#pragma unroll
    for (int s = 0; s < 2; s++) {
        float w = g_gate[s][t];
        if (w != 0.f) {
            int e = g_exp[s][t];
            float d0 = g_acc[t][s][0], d1 = g_acc[t][s][1];
            float a0 = g_acc[t][s][2], a1 = g_acc[t][s][3];
            float z0 = d0 + LSCALE * (a0 * g_b2wh[e * 4 + 0] + a1 * g_b2wh[e * 4 + 2]);
            float z1 = d1 + LSCALE * (a0 * g_b2wh[e * 4 + 1] + a1 * g_b2wh[e * 4 + 3]);
            s0 += w * z0; s1 += w * z1;
        }
    }
    red[tid][0] = s0; red[tid][1] = s1;
    __syncthreads();
    for (int o = 128; o; o >>= 1) {
        if (tid < o) { red[tid][0] += red[tid + o][0]; red[tid][1] += red[tid + o][1]; }
        __syncthreads();
    }
    if (tid == 0) { g_part[b][part][0] = red[0][0]; g_part[b][part][1] = red[0][1]; }
}

__global__ void final_sum_kernel(const float* __restrict__ bh, float* __restrict__ out) {
    int tid = threadIdx.x;
    if (tid < NBATCH * 2) {
        int b = tid >> 1, c = tid & 1;
        float s = 0.f;
#pragma unroll
        for (int p = 0; p < 8; p++) s += g_part[b][p][c];
        out[b * 2 + c] = s / (float)SEQ + bh[c];
    }
}

// ---------------- launch ----------------
extern "C" void kernel_launch(void* const* d_in, const int* in_sizes, int n_in,
                              void* d_out, int out_size) {
    const float* x  = (const float*)d_in[0];
    const float* Wg = (const float*)d_in[1];
    const float* W1 = (const float*)d_in[2];
    const float* W2 = (const float*)d_in[3];
    const float* A1 = (const float*)d_in[4];
    const float* B1 = (const float*)d_in[5];
    const float* A2 = (const float*)d_in[6];
    const float* B2 = (const float*)d_in[7];
    const float* Wh = (const float*)d_in[8];
    const float* bh = (const float*)d_in[9];

    cudaFuncSetAttribute(ffn_tc_kernel, cudaFuncAttributeMaxDynamicSharedMemorySize, SMEM_REQ);

    aux_kernel<<<GATE_BLOCKS + CONVW_BLOCKS + PREP_BLOCKS, 256>>>(x, Wg, A1, W1, W2, Wh, B2);
    route_kernel<<<1, 1024>>>();
    ffn_tc_kernel<<<dim3(FFDIM / GBN, T_TOK / GBM), NTHR, SMEM_REQ>>>(B1, A2);
    final_part_kernel<<<dim3(8, NBATCH), 256>>>();
    final_sum_kernel<<<1, 32>>>(bh, (float*)d_out);
}

// round 14
// speedup vs baseline: 1.0156x; 1.0156x over previous
#include <cuda_runtime.h>
#include <cuda_bf16.h>
#include <math.h>

// ---------------- problem constants ----------------
#define T_TOK 8192
#define DMODEL 1024
#define FFDIM 4096
#define NEXP 8
#define CAP 2560
#define SEQ 2048
#define NBATCH 4
#define LSCALE 2.0f

// ---------------- device scratch ----------------
__device__ float g_w2wh[FFDIM * 2];
__device__ float g_b2wh[NEXP * 2 * 2];
__device__ int   g_exp[2][T_TOK];
__device__ float g_gate[2][T_TOK];
__device__ float g_u1[2][T_TOK][2];
__device__ float g_acc[T_TOK][2][4];
__device__ int   g_cnt[NEXP];                  // zeroed by route_kernel each launch
__device__ float g_part[NBATCH][8][2];

__device__ __nv_bfloat16 g_xhi[T_TOK * DMODEL];
__device__ __nv_bfloat16 g_xlo[T_TOK * DMODEL];
__device__ __nv_bfloat16 g_w1t_hi[FFDIM * DMODEL];
__device__ __nv_bfloat16 g_w1t_lo[FFDIM * DMODEL];

// ---------------- PTX helpers ----------------
__device__ __forceinline__ unsigned smem_u32(const void* p) {
    unsigned a;
    asm("{ .reg .u64 t; cvta.to.shared.u64 t, %1; cvt.u32.u64 %0, t; }" : "=r"(a) : "l"(p));
    return a;
}
#define CP_ASYNC16(saddr, gptr) \
    asm volatile("cp.async.cg.shared.global [%0], [%1], 16;" :: "r"(saddr), "l"(gptr))
#define CP_COMMIT() asm volatile("cp.async.commit_group;" ::: "memory")
#define CP_WAIT1()  asm volatile("cp.async.wait_group 1;" ::: "memory")
#define CP_WAIT0()  asm volatile("cp.async.wait_group 0;" ::: "memory")

__device__ __forceinline__ void ldmx4(unsigned addr, unsigned& r0, unsigned& r1,
                                      unsigned& r2, unsigned& r3) {
    asm volatile("ldmatrix.sync.aligned.m8n8.x4.shared.b16 {%0,%1,%2,%3}, [%4];"
                 : "=r"(r0), "=r"(r1), "=r"(r2), "=r"(r3) : "r"(addr));
}
__device__ __forceinline__ void mma16816(float* c, const unsigned* a, const unsigned* b) {
    asm volatile("mma.sync.aligned.m16n8k16.row.col.f32.bf16.bf16.f32 "
                 "{%0,%1,%2,%3}, {%4,%5,%6,%7}, {%8,%9}, {%0,%1,%2,%3};"
                 : "+f"(c[0]), "+f"(c[1]), "+f"(c[2]), "+f"(c[3])
                 : "r"(a[0]), "r"(a[1]), "r"(a[2]), "r"(a[3]), "r"(b[0]), "r"(b[1]));
}

// ---------------- merged aux kernel: gate | convert_w | prep ----------------
#define GATE_BLOCKS 1024
#define CONVW_BLOCKS 4096
#define PREP_BLOCKS 513

__global__ void aux_kernel(const float* __restrict__ x,  const float* __restrict__ Wg,
                           const float* __restrict__ A1, const float* __restrict__ W1,
                           const float* __restrict__ W2, const float* __restrict__ Wh,
                           const float* __restrict__ B2) {
    __shared__ float sbuf[NEXP * DMODEL];     // 32 KB, reused per role
    int bid = blockIdx.x, tid = threadIdx.x;

    if (bid < GATE_BLOCKS) {
        // ---- gating + u1 + x hi/lo conversion + hist + zero accum, x in registers ----
        float (*wgt)[DMODEL] = (float(*)[DMODEL])sbuf;
        for (int i = tid; i < DMODEL * NEXP; i += 256) {
            int d = i >> 3, e = i & 7;
            wgt[e][d] = Wg[i];
        }
        __syncthreads();

        int warp = tid >> 5, lane = tid & 31;
        int t = bid * 8 + warp;
        const float* xr = x + (size_t)t * DMODEL;

        float4 xv[8];
#pragma unroll
        for (int i = 0; i < 8; i++) xv[i] = *(const float4*)(xr + i * 128 + lane * 4);

#pragma unroll
        for (int i = 0; i < 8; i++) {
            int d = i * 128 + lane * 4;
            __nv_bfloat16 h0 = __float2bfloat16(xv[i].x), h1 = __float2bfloat16(xv[i].y);
            __nv_bfloat16 h2 = __float2bfloat16(xv[i].z), h3 = __float2bfloat16(xv[i].w);
            __nv_bfloat162 hi01 = __halves2bfloat162(h0, h1);
            __nv_bfloat162 hi23 = __halves2bfloat162(h2, h3);
            __nv_bfloat162 lo01 = __floats2bfloat162_rn(xv[i].x - __bfloat162float(h0),
                                                        xv[i].y - __bfloat162float(h1));
            __nv_bfloat162 lo23 = __floats2bfloat162_rn(xv[i].z - __bfloat162float(h2),
                                                        xv[i].w - __bfloat162float(h3));
            uint2 hv, lv;
            hv.x = *(unsigned*)&hi01; hv.y = *(unsigned*)&hi23;
            lv.x = *(unsigned*)&lo01; lv.y = *(unsigned*)&lo23;
            *(uint2*)(g_xhi + (size_t)t * DMODEL + d) = hv;
            *(uint2*)(g_xlo + (size_t)t * DMODEL + d) = lv;
        }

        float lg[8] = {};
#pragma unroll
        for (int e = 0; e < 8; e++) {
#pragma unroll
            for (int i = 0; i < 8; i++) {
                float4 wv = *(const float4*)&wgt[e][i * 128 + lane * 4];
                lg[e] += xv[i].x * wv.x + xv[i].y * wv.y + xv[i].z * wv.z + xv[i].w * wv.w;
            }
        }
#pragma unroll
        for (int e = 0; e < 8; e++)
            for (int o = 16; o; o >>= 1) lg[e] += __shfl_xor_sync(~0u, lg[e], o);

        float v0 = -1e30f, v1 = -1e30f; int e0 = 0, e1 = 0;
#pragma unroll
        for (int e = 0; e < 8; e++) {
            float l = lg[e];
            if (l > v0)      { v1 = v0; e1 = e0; v0 = l; e0 = e; }
            else if (l > v1) { v1 = l;  e1 = e; }
        }
        float q  = expf(v1 - v0);
        float g0 = 1.0f / (1.0f + q);
        float g1 = q * g0;

        float u00 = 0.f, u01 = 0.f, u10 = 0.f, u11 = 0.f;
        const float* a1e0 = A1 + (size_t)e0 * DMODEL * 2;
        const float* a1e1 = A1 + (size_t)e1 * DMODEL * 2;
#pragma unroll
        for (int i = 0; i < 8; i++) {
            int base = 2 * (i * 128 + lane * 4);
            float4 p0 = *(const float4*)(a1e0 + base);
            float4 p1 = *(const float4*)(a1e0 + base + 4);
            u00 += xv[i].x * p0.x + xv[i].y * p0.z + xv[i].z * p1.x + xv[i].w * p1.z;
            u01 += xv[i].x * p0.y + xv[i].y * p0.w + xv[i].z * p1.y + xv[i].w * p1.w;
            float4 q0 = *(const float4*)(a1e1 + base);
            float4 q1 = *(const float4*)(a1e1 + base + 4);
            u10 += xv[i].x * q0.x + xv[i].y * q0.z + xv[i].z * q1.x + xv[i].w * q1.z;
            u11 += xv[i].x * q0.y + xv[i].y * q0.w + xv[i].z * q1.y + xv[i].w * q1.w;
        }
        for (int o = 16; o; o >>= 1) {
            u00 += __shfl_xor_sync(~0u, u00, o); u01 += __shfl_xor_sync(~0u, u01, o);
            u10 += __shfl_xor_sync(~0u, u10, o); u11 += __shfl_xor_sync(~0u, u11, o);
        }
        if (lane == 0) {
            g_exp[0][t] = e0;  g_exp[1][t] = e1;
            g_gate[0][t] = g0; g_gate[1][t] = g1;
            g_u1[0][t][0] = LSCALE * u00; g_u1[0][t][1] = LSCALE * u01;
            g_u1[1][t][0] = LSCALE * u10; g_u1[1][t][1] = LSCALE * u11;
            atomicAdd(&g_cnt[e0], 1);
            atomicAdd(&g_cnt[e1], 1);
        }
        if (lane < 8) (&g_acc[t][0][0])[lane] = 0.f;
    } else if (bid < GATE_BLOCKS + CONVW_BLOCKS) {
        // ---- W1 -> transposed bf16 hi/lo (4-byte stores) ----
        float (*tile)[33] = (float(*)[33])sbuf;
        int idx = bid - GATE_BLOCKS;
        int bx = idx & 127, by = idx >> 7;
        int tx = tid & 31, ty = tid >> 5;
#pragma unroll
        for (int i = 0; i < 4; i++) {
            int k = by * 32 + ty + i * 8, n = bx * 32 + tx;
            tile[ty + i * 8][tx] = W1[(size_t)k * FFDIM + n];
        }
        __syncthreads();
#pragma unroll
        for (int i = 0; i < 2; i++) {
            int u = i * 256 + tid;               // 512 (n, k-pair) units
            int nl = u >> 4, kp = u & 15;
            int n = bx * 32 + nl;
            int k = by * 32 + kp * 2;
            float v0 = tile[kp * 2][nl], v1 = tile[kp * 2 + 1][nl];
            __nv_bfloat16 h0 = __float2bfloat16(v0), h1 = __float2bfloat16(v1);
            __nv_bfloat162 hv = __halves2bfloat162(h0, h1);
            __nv_bfloat162 lv = __floats2bfloat162_rn(v0 - __bfloat162float(h0),
                                                      v1 - __bfloat162float(h1));
            *(__nv_bfloat162*)(g_w1t_hi + (size_t)n * DMODEL + k) = hv;
            *(__nv_bfloat162*)(g_w1t_lo + (size_t)n * DMODEL + k) = lv;
        }
    } else {
        // ---- prep: head-folded matrices ----
        int pb = bid - GATE_BLOCKS - CONVW_BLOCKS;
        int gw = pb * 8 + (tid >> 5);
        int lane = tid & 31;
        if (gw < FFDIM) {
            const float* wr = W2 + (size_t)gw * DMODEL;
            float s0 = 0.f, s1 = 0.f;
            for (int d = lane; d < DMODEL; d += 32) {
                float wv = wr[d];
                s0 += wv * Wh[2 * d]; s1 += wv * Wh[2 * d + 1];
            }
            for (int o = 16; o; o >>= 1) {
                s0 += __shfl_xor_sync(~0u, s0, o); s1 += __shfl_xor_sync(~0u, s1, o);
            }
            if (lane == 0) { g_w2wh[2 * gw] = s0; g_w2wh[2 * gw + 1] = s1; }
        } else {
            int w = gw - FFDIM;
            for (int p = 2 * w; p < 2 * w + 2 && p < 16; p++) {
                const float* br = B2 + (size_t)p * DMODEL;
                float s0 = 0.f, s1 = 0.f;
                for (int d = lane; d < DMODEL; d += 32) {
                    float bv = br[d];
                    s0 += bv * Wh[2 * d]; s1 += bv * Wh[2 * d + 1];
                }
                for (int o = 16; o; o >>= 1) {
                    s0 += __shfl_xor_sync(~0u, s0, o); s1 += __shfl_xor_sync(~0u, s1, o);
                }
                if (lane == 0) { g_b2wh[2 * p] = s0; g_b2wh[2 * p + 1] = s1; }
            }
        }
    }
}

// ---------------- kernel: capacity scan (fast path) + g_cnt reset ----------------
__global__ void route_kernel() {
    int tid = threadIdx.x;
    bool over = false;
#pragma unroll
    for (int e = 0; e < 8; e++) over |= (g_cnt[e] > CAP);
    __syncthreads();
    if (tid < 8) g_cnt[tid] = 0;
    if (!over) return;

    int lane = tid & 31, warp = tid >> 5;
    int base = tid * 16;

    unsigned char le[16];
    int cnt[8] = {};
    for (int j = 0; j < 16; j++) {
        int a = base + j;
        int s = a >> 13, t = a & (T_TOK - 1);
        int e = g_exp[s][t];
        le[j] = (unsigned char)e;
        cnt[e]++;
    }
    __shared__ int warpsum[32][8];
    int excl[8];
#pragma unroll
    for (int e = 0; e < 8; e++) {
        int v = cnt[e], inc = v;
        for (int o = 1; o < 32; o <<= 1) {
            int nv = __shfl_up_sync(~0u, inc, o);
            if (lane >= o) inc += nv;
        }
        excl[e] = inc - v;
        if (lane == 31) warpsum[warp][e] = inc;
    }
    __syncthreads();
    if (warp == 0) {
#pragma unroll
        for (int e = 0; e < 8; e++) {
            int v = warpsum[lane][e], inc = v;
            for (int o = 1; o < 32; o <<= 1) {
                int nv = __shfl_up_sync(~0u, inc, o);
                if (lane >= o) inc += nv;
            }
            warpsum[lane][e] = inc - v;
        }
    }
    __syncthreads();
#pragma unroll
    for (int e = 0; e < 8; e++) excl[e] += warpsum[warp][e];

    for (int j = 0; j < 16; j++) {
        int a = base + j;
        int s = a >> 13, t = a & (T_TOK - 1);
        int e = le[j];
        int pos = excl[e]++;
        if (pos >= CAP) g_gate[s][t] = 0.f;
    }
}

// ---------------- HMMA GEMM, term-inner (128x256 CTA, 4x4 warps of 32x64) -------
#define GBM 128
#define GBN 256
#define GKC 64
#define NCHUNK 16
#define A_BYTES 32768
#define B_BYTES 65536
#define STAGE_BYTES (A_BYTES + B_BYTES)
#define NSTAGE 2
#define SMEM_REQ (NSTAGE * STAGE_BYTES)   // 192 KB, 1 CTA/SM, 16 warps
#define NTHR 512

__device__ __forceinline__ void issue_stage(unsigned sbase, int chunk, int mBase, int nBase,
                                            int tid) {
    int k0 = chunk * GKC;
#pragma unroll
    for (int q = 0; q < 4; q++) {
        int u = q * NTHR + tid;
        int row = u >> 3, ch = u & 7;
        const __nv_bfloat16* ap = (q < 2) ? (g_xhi + (size_t)(mBase + row) * DMODEL)
                                          : (g_xlo + (size_t)(mBase + row - 128) * DMODEL);
        unsigned off = row * 128 + (((unsigned)(ch ^ (row & 7))) << 4);
        CP_ASYNC16(sbase + off, ap + k0 + ch * 8);
    }
#pragma unroll
    for (int q = 0; q < 8; q++) {
        int u = q * NTHR + tid;
        int row = u >> 3, ch = u & 7;
        const __nv_bfloat16* bp = (q < 4) ? (g_w1t_hi + (size_t)(nBase + row) * DMODEL)
                                          : (g_w1t_lo + (size_t)(nBase + row - 256) * DMODEL);
        unsigned off = A_BYTES + row * 128 + (((unsigned)(ch ^ (row & 7))) << 4);
        CP_ASYNC16(sbase + off, bp + k0 + ch * 8);
    }
}

__global__ __launch_bounds__(NTHR, 1)
void ffn_tc_kernel(const float* __restrict__ B1, const float* __restrict__ A2) {
    extern __shared__ char dsm[];
    unsigned sbase = smem_u32(dsm);

    int tid = threadIdx.x, wid = tid >> 5, lane = tid & 31;
    int wm = wid & 3, wn = wid >> 2;
    int mBase = blockIdx.y * GBM, nBase = blockIdx.x * GBN;

    float acc[2][8][4] = {};

    issue_stage(sbase + 0 * STAGE_BYTES, 0, mBase, nBase, tid); CP_COMMIT();
    issue_stage(sbase + 1 * STAGE_BYTES, 1, mBase, nBase, tid); CP_COMMIT();

    int grp = lane >> 3, r8 = lane & 7;
    int a_m  = wm * 32 + (grp & 1) * 8 + r8;
    int a_ch = grp >> 1;
    int b_n  = wn * 64 + (grp >> 1) * 8 + r8;
    int b_ch = grp & 1;

    for (int c = 0; c < NCHUNK; c++) {
        if (c >= NCHUNK - 1) { CP_WAIT0(); } else { CP_WAIT1(); }
        __syncthreads();
        unsigned st = sbase + (c & 1) * STAGE_BYTES;
#pragma unroll
        for (int ks = 0; ks < 4; ks++) {
            unsigned ah[2][4], al[2][4];
#pragma unroll
            for (int mf = 0; mf < 2; mf++) {
                int m = a_m + mf * 16;
                int ch = 2 * ks + a_ch;
                unsigned sw = (((unsigned)(ch ^ (m & 7))) << 4);
                ldmx4(st + m * 128 + sw, ah[mf][0], ah[mf][1], ah[mf][2], ah[mf][3]);
                ldmx4(st + (m + 128) * 128 + sw, al[mf][0], al[mf][1], al[mf][2], al[mf][3]);
            }
            unsigned b[8][2];
#pragma unroll
            for (int nf2 = 0; nf2 < 4; nf2++) {
                int n = b_n + nf2 * 16;
                int ch = 2 * ks + b_ch;
                unsigned addr = st + A_BYTES + n * 128 + (((unsigned)(ch ^ (n & 7))) << 4);
                ldmx4(addr, b[nf2 * 2][0], b[nf2 * 2][1], b[nf2 * 2 + 1][0], b[nf2 * 2 + 1][1]);
            }
#pragma unroll
            for (int mf = 0; mf < 2; mf++)
#pragma unroll
                for (int nf = 0; nf < 8; nf++) {
                    mma16816(acc[mf][nf], ah[mf], b[nf]);   // x_hi . W_hi
                    mma16816(acc[mf][nf], al[mf], b[nf]);   // x_lo . W_hi
                }
#pragma unroll
            for (int nf2 = 0; nf2 < 4; nf2++) {
                int n = b_n + nf2 * 16 + 256;
                int ch = 2 * ks + b_ch;
                unsigned addr = st + A_BYTES + n * 128 + (((unsigned)(ch ^ (n & 7))) << 4);
                ldmx4(addr, b[nf2 * 2][0], b[nf2 * 2][1], b[nf2 * 2 + 1][0], b[nf2 * 2 + 1][1]);
            }
#pragma unroll
            for (int mf = 0; mf < 2; mf++)
#pragma unroll
                for (int nf = 0; nf < 8; nf++)
                    mma16816(acc[mf][nf], ah[mf], b[nf]);   // x_hi . W_lo
        }
        __syncthreads();
        if (c + 2 < NCHUNK) {
            issue_stage(sbase + (c & 1) * STAGE_BYTES, c + 2, mBase, nBase, tid);
            CP_COMMIT();
        }
    }

    // ---- epilogue ----
    float* ep_w  = (float*)dsm;                       // [256][33]
    float* ep_w2 = (float*)(dsm + 33792);             // [256][2]
    float* ep_g  = (float*)(dsm + 35840);             // [2][128]
    float* ep_u  = (float*)(dsm + 36864);             // [2][128][2]
    int*   ep_e  = (int*)  (dsm + 38912);             // [2][128]

#pragma unroll
    for (int it = 0; it < 16; it++) {
        int idx = it * NTHR + tid;
        int n = idx >> 5, e = (idx >> 2) & 7, q = idx & 3;
        float v;
        if (q < 2) v = B1[(size_t)(e * 2 + q) * FFDIM + nBase + n];
        else       v = A2[(size_t)e * FFDIM * 2 + (size_t)(nBase + n) * 2 + (q - 2)];
        ep_w[n * 33 + e * 4 + q] = v;
    }
    ep_w2[tid] = g_w2wh[nBase * 2 + tid];
    if (tid < 256) {
        int s = tid >> 7, m = tid & 127;
        int t = mBase + m;
        ep_g[s * 128 + m] = g_gate[s][t];
        ep_e[s * 128 + m] = g_exp[s][t];
        ep_u[(s * 128 + m) * 2 + 0] = g_u1[s][t][0];
        ep_u[(s * 128 + m) * 2 + 1] = g_u1[s][t][1];
    }
    __syncthreads();

    const float GC  = 0.7978845608028654f;
    const float T2L = 2.8853900817779268f;
    int quad = lane >> 2, qi = lane & 3;

#pragma unroll
    for (int mf = 0; mf < 2; mf++) {
#pragma unroll
        for (int q8 = 0; q8 < 2; q8++) {
            int m = wm * 32 + mf * 16 + q8 * 8 + quad;
            int t = mBase + m;
#pragma unroll
            for (int s = 0; s < 2; s++) {
                float w = ep_g[s * 128 + m];
                float p0 = 0.f, p1 = 0.f, p2 = 0.f, p3 = 0.f;
                if (w != 0.f) {
                    int e = ep_e[s * 128 + m];
                    float u0 = ep_u[(s * 128 + m) * 2 + 0];
                    float u1 = ep_u[(s * 128 + m) * 2 + 1];
                    const float* wb = ep_w + e * 4;
#pragma unroll
                    for (int nf = 0; nf < 8; nf++) {
#pragma unroll
                        for (int r = 0; r < 2; r++) {
                            int n = wn * 64 + nf * 8 + 2 * qi + r;
                            float av = acc[mf][nf][q8 * 2 + r];
                            float b1r0 = wb[n * 33 + 0], b1r1 = wb[n * 33 + 1];
                            float v = av + u0 * b1r0 + u1 * b1r1;
                            float yy = GC * (v + 0.044715f * v * v * v);
                            float ex = exp2f(yy * T2L);
                            float th = 1.0f - __fdividef(2.0f, ex + 1.0f);
                            float h  = 0.5f * v * (1.0f + th);
                            p0 += h * ep_w2[n * 2];
                            p1 += h * ep_w2[n * 2 + 1];
                            p2 += h * wb[n * 33 + 2];
                            p3 += h * wb[n * 33 + 3];
                        }
                    }
                }
                for (int o = 1; o <= 2; o <<= 1) {
                    p0 += __shfl_xor_sync(~0u, p0, o);
                    p1 += __shfl_xor_sync(~0u, p1, o);
                    p2 += __shfl_xor_sync(~0u, p2, o);
                    p3 += __shfl_xor_sync(~0u, p3, o);
                }
                if (qi == 0 && w != 0.f) {
                    atomicAdd(&g_acc[t][s][0], p0);
                    atomicAdd(&g_acc[t][s][1], p1);
                    atomicAdd(&g_acc[t][s][2], p2);
                    atomicAdd(&g_acc[t][s][3], p3);
                }
            }
        }
    }
}

// ---------------- combine + pool: two-stage deterministic reduction ----------------
__global__ void final_part_kernel() {
    __shared__ float red[256][2];
    int part = blockIdx.x, b = blockIdx.y, tid = threadIdx.x;
    int t = b * SEQ + part * 256 + tid;
    float s0 = 0.f, s1 = 0.f;
#pragma unroll
    for (int s = 0; s < 2; s++) {
        float w = g_gate[s][t];
        if (w != 0.f) {
            int e = g_exp[s][t];
            float d0 = g_acc[t][s][0], d1 = g_acc[t][s][1];
            float a0 = g_acc[t][s][2], a1 = g_acc[t][s][3];
            float z0 = d0 + LSCALE * (a0 * g_b2wh[e * 4 + 0] + a1 * g_b2wh[e * 4 + 2]);
            float z1 = d1 + LSCALE * (a0 * g_b2wh[e * 4 + 1] + a1 * g_b2wh[e * 4 + 3]);
            s0 += w * z0; s1 += w * z1;
        }
    }
    red[tid][0] = s0; red[tid][1] = s1;
    __syncthreads();
    for (int o = 128; o; o >>= 1) {
        if (tid < o) { red[tid][0] += red[tid + o][0]; red[tid][1] += red[tid + o][1]; }
        __syncthreads();
    }
    if (tid == 0) { g_part[b][part][0] = red[0][0]; g_part[b][part][1] = red[0][1]; }
}

__global__ void final_sum_kernel(const float* __restrict__ bh, float* __restrict__ out) {
    int tid = threadIdx.x;
    if (tid < NBATCH * 2) {
        int b = tid >> 1, c = tid & 1;
        float s = 0.f;
#pragma unroll
        for (int p = 0; p < 8; p++) s += g_part[b][p][c];
        out[b * 2 + c] = s / (float)SEQ + bh[c];
    }
}

// ---------------- launch ----------------
extern "C" void kernel_launch(void* const* d_in, const int* in_sizes, int n_in,
                              void* d_out, int out_size) {
    const float* x  = (const float*)d_in[0];
    const float* Wg = (const float*)d_in[1];
    const float* W1 = (const float*)d_in[2];
    const float* W2 = (const float*)d_in[3];
    const float* A1 = (const float*)d_in[4];
    const float* B1 = (const float*)d_in[5];
    const float* A2 = (const float*)d_in[6];
    const float* B2 = (const float*)d_in[7];
    const float* Wh = (const float*)d_in[8];
    const float* bh = (const float*)d_in[9];

    cudaFuncSetAttribute(ffn_tc_kernel, cudaFuncAttributeMaxDynamicSharedMemorySize, SMEM_REQ);

    aux_kernel<<<GATE_BLOCKS + CONVW_BLOCKS + PREP_BLOCKS, 256>>>(x, Wg, A1, W1, W2, Wh, B2);
    route_kernel<<<1, 1024>>>();
    ffn_tc_kernel<<<dim3(FFDIM / GBN, T_TOK / GBM), NTHR, SMEM_REQ>>>(B1, A2);
    final_part_kernel<<<dim3(8, NBATCH), 256>>>();
    final_sum_kernel<<<1, 32>>>(bh, (float*)d_out);
}

// round 15
// speedup vs baseline: 1.3535x; 1.3327x over previous
#include <cuda_runtime.h>
#include <cuda_fp16.h>
#include <math.h>

// ---------------- problem constants ----------------
#define T_TOK 8192
#define DMODEL 1024
#define FFDIM 4096
#define NEXP 8
#define CAP 2560
#define SEQ 2048
#define NBATCH 4
#define LSCALE 2.0f

// ---------------- device scratch ----------------
__device__ float g_w2wh[FFDIM * 2];
__device__ float g_b2wh[NEXP * 2 * 2];
__device__ int   g_exp[2][T_TOK];
__device__ float g_gate[2][T_TOK];
__device__ float g_u1[2][T_TOK][2];
__device__ float g_acc[T_TOK][2][4];
__device__ int   g_cnt[NEXP];
__device__ float g_part[NBATCH][8][2];

__device__ __half g_xhi[T_TOK * DMODEL];      // fp16 high part of x
__device__ __half g_xlo[T_TOK * DMODEL];      // fp16 residual of x
__device__ __half g_w1t[FFDIM * DMODEL];      // W1 transposed, fp16 (single copy)

// ---------------- PTX helpers ----------------
__device__ __forceinline__ unsigned smem_u32(const void* p) {
    unsigned a;
    asm("{ .reg .u64 t; cvta.to.shared.u64 t, %1; cvt.u32.u64 %0, t; }" : "=r"(a) : "l"(p));
    return a;
}
#define CP_ASYNC16(saddr, gptr) \
    asm volatile("cp.async.cg.shared.global [%0], [%1], 16;" :: "r"(saddr), "l"(gptr))
#define CP_COMMIT() asm volatile("cp.async.commit_group;" ::: "memory")
#define CP_WAIT1()  asm volatile("cp.async.wait_group 1;" ::: "memory")
#define CP_WAIT0()  asm volatile("cp.async.wait_group 0;" ::: "memory")

__device__ __forceinline__ void ldmx4(unsigned addr, unsigned& r0, unsigned& r1,
                                      unsigned& r2, unsigned& r3) {
    asm volatile("ldmatrix.sync.aligned.m8n8.x4.shared.b16 {%0,%1,%2,%3}, [%4];"
                 : "=r"(r0), "=r"(r1), "=r"(r2), "=r"(r3) : "r"(addr));
}
__device__ __forceinline__ void mma16816h(float* c, const unsigned* a, const unsigned* b) {
    asm volatile("mma.sync.aligned.m16n8k16.row.col.f32.f16.f16.f32 "
                 "{%0,%1,%2,%3}, {%4,%5,%6,%7}, {%8,%9}, {%0,%1,%2,%3};"
                 : "+f"(c[0]), "+f"(c[1]), "+f"(c[2]), "+f"(c[3])
                 : "r"(a[0]), "r"(a[1]), "r"(a[2]), "r"(a[3]), "r"(b[0]), "r"(b[1]));
}

// ---------------- merged aux kernel: gate | convert_w | prep ----------------
#define GATE_BLOCKS 1024
#define CONVW_BLOCKS 4096
#define PREP_BLOCKS 513

__global__ void aux_kernel(const float* __restrict__ x,  const float* __restrict__ Wg,
                           const float* __restrict__ A1, const float* __restrict__ W1,
                           const float* __restrict__ W2, const float* __restrict__ Wh,
                           const float* __restrict__ B2) {
    __shared__ float sbuf[NEXP * DMODEL];     // 32 KB, reused per role
    int bid = blockIdx.x, tid = threadIdx.x;

    if (bid < GATE_BLOCKS) {
        // ---- gating + u1 + x fp16 hi/lo conversion + hist + zero accum ----
        float (*wgt)[DMODEL] = (float(*)[DMODEL])sbuf;
        for (int i = tid; i < DMODEL * NEXP; i += 256) {
            int d = i >> 3, e = i & 7;
            wgt[e][d] = Wg[i];
        }
        __syncthreads();

        int warp = tid >> 5, lane = tid & 31;
        int t = bid * 8 + warp;
        const float* xr = x + (size_t)t * DMODEL;

        float4 xv[8];
#pragma unroll
        for (int i = 0; i < 8; i++) xv[i] = *(const float4*)(xr + i * 128 + lane * 4);

#pragma unroll
        for (int i = 0; i < 8; i++) {
            int d = i * 128 + lane * 4;
            __half h0 = __float2half(xv[i].x), h1 = __float2half(xv[i].y);
            __half h2 = __float2half(xv[i].z), h3 = __float2half(xv[i].w);
            __half l0 = __float2half(xv[i].x - __half2float(h0));
            __half l1 = __float2half(xv[i].y - __half2float(h1));
            __half l2 = __float2half(xv[i].z - __half2float(h2));
            __half l3 = __float2half(xv[i].w - __half2float(h3));
            __half2 hi01 = __halves2half2(h0, h1), hi23 = __halves2half2(h2, h3);
            __half2 lo01 = __halves2half2(l0, l1), lo23 = __halves2half2(l2, l3);
            uint2 hv, lv;
            hv.x = *(unsigned*)&hi01; hv.y = *(unsigned*)&hi23;
            lv.x = *(unsigned*)&lo01; lv.y = *(unsigned*)&lo23;
            *(uint2*)(g_xhi + (size_t)t * DMODEL + d) = hv;
            *(uint2*)(g_xlo + (size_t)t * DMODEL + d) = lv;
        }

        float lg[8] = {};
#pragma unroll
        for (int e = 0; e < 8; e++) {
#pragma unroll
            for (int i = 0; i < 8; i++) {
                float4 wv = *(const float4*)&wgt[e][i * 128 + lane * 4];
                lg[e] += xv[i].x * wv.x + xv[i].y * wv.y + xv[i].z * wv.z + xv[i].w * wv.w;
            }
        }
#pragma unroll
        for (int e = 0; e < 8; e++)
            for (int o = 16; o; o >>= 1) lg[e] += __shfl_xor_sync(~0u, lg[e], o);

        float v0 = -1e30f, v1 = -1e30f; int e0 = 0, e1 = 0;
#pragma unroll
        for (int e = 0; e < 8; e++) {
            float l = lg[e];
            if (l > v0)      { v1 = v0; e1 = e0; v0 = l; e0 = e; }
            else if (l > v1) { v1 = l;  e1 = e; }
        }
        float q  = expf(v1 - v0);
        float g0 = 1.0f / (1.0f + q);
        float g1 = q * g0;

        float u00 = 0.f, u01 = 0.f, u10 = 0.f, u11 = 0.f;
        const float* a1e0 = A1 + (size_t)e0 * DMODEL * 2;
        const float* a1e1 = A1 + (size_t)e1 * DMODEL * 2;
#pragma unroll
        for (int i = 0; i < 8; i++) {
            int base = 2 * (i * 128 + lane * 4);
            float4 p0 = *(const float4*)(a1e0 + base);
            float4 p1 = *(const float4*)(a1e0 + base + 4);
            u00 += xv[i].x * p0.x + xv[i].y * p0.z + xv[i].z * p1.x + xv[i].w * p1.z;
            u01 += xv[i].x * p0.y + xv[i].y * p0.w + xv[i].z * p1.y + xv[i].w * p1.w;
            float4 q0 = *(const float4*)(a1e1 + base);
            float4 q1 = *(const float4*)(a1e1 + base + 4);
            u10 += xv[i].x * q0.x + xv[i].y * q0.z + xv[i].z * q1.x + xv[i].w * q1.z;
            u11 += xv[i].x * q0.y + xv[i].y * q0.w + xv[i].z * q1.y + xv[i].w * q1.w;
        }
        for (int o = 16; o; o >>= 1) {
            u00 += __shfl_xor_sync(~0u, u00, o); u01 += __shfl_xor_sync(~0u, u01, o);
            u10 += __shfl_xor_sync(~0u, u10, o); u11 += __shfl_xor_sync(~0u, u11, o);
        }
        if (lane == 0) {
            g_exp[0][t] = e0;  g_exp[1][t] = e1;
            g_gate[0][t] = g0; g_gate[1][t] = g1;
            g_u1[0][t][0] = LSCALE * u00; g_u1[0][t][1] = LSCALE * u01;
            g_u1[1][t][0] = LSCALE * u10; g_u1[1][t][1] = LSCALE * u11;
            atomicAdd(&g_cnt[e0], 1);
            atomicAdd(&g_cnt[e1], 1);
        }
        if (lane < 8) (&g_acc[t][0][0])[lane] = 0.f;
    } else if (bid < GATE_BLOCKS + CONVW_BLOCKS) {
        // ---- W1 -> transposed fp16 (single copy, 4-byte stores) ----
        float (*tile)[33] = (float(*)[33])sbuf;
        int idx = bid - GATE_BLOCKS;
        int bx = idx & 127, by = idx >> 7;
        int tx = tid & 31, ty = tid >> 5;
#pragma unroll
        for (int i = 0; i < 4; i++) {
            int k = by * 32 + ty + i * 8, n = bx * 32 + tx;
            tile[ty + i * 8][tx] = W1[(size_t)k * FFDIM + n];
        }
        __syncthreads();
#pragma unroll
        for (int i = 0; i < 2; i++) {
            int u = i * 256 + tid;               // 512 (n, k-pair) units
            int nl = u >> 4, kp = u & 15;
            int n = bx * 32 + nl;
            int k = by * 32 + kp * 2;
            __half2 hv = __halves2half2(__float2half(tile[kp * 2][nl]),
                                        __float2half(tile[kp * 2 + 1][nl]));
            *(__half2*)(g_w1t + (size_t)n * DMODEL + k) = hv;
        }
    } else {
        // ---- prep: head-folded matrices ----
        int pb = bid - GATE_BLOCKS - CONVW_BLOCKS;
        int gw = pb * 8 + (tid >> 5);
        int lane = tid & 31;
        if (gw < FFDIM) {
            const float* wr = W2 + (size_t)gw * DMODEL;
            float s0 = 0.f, s1 = 0.f;
            for (int d = lane; d < DMODEL; d += 32) {
                float wv = wr[d];
                s0 += wv * Wh[2 * d]; s1 += wv * Wh[2 * d + 1];
            }
            for (int o = 16; o; o >>= 1) {
                s0 += __shfl_xor_sync(~0u, s0, o); s1 += __shfl_xor_sync(~0u, s1, o);
            }
            if (lane == 0) { g_w2wh[2 * gw] = s0; g_w2wh[2 * gw + 1] = s1; }
        } else {
            int w = gw - FFDIM;
            for (int p = 2 * w; p < 2 * w + 2 && p < 16; p++) {
                const float* br = B2 + (size_t)p * DMODEL;
                float s0 = 0.f, s1 = 0.f;
                for (int d = lane; d < DMODEL; d += 32) {
                    float bv = br[d];
                    s0 += bv * Wh[2 * d]; s1 += bv * Wh[2 * d + 1];
                }
                for (int o = 16; o; o >>= 1) {
                    s0 += __shfl_xor_sync(~0u, s0, o); s1 += __shfl_xor_sync(~0u, s1, o);
                }
                if (lane == 0) { g_b2wh[2 * p] = s0; g_b2wh[2 * p + 1] = s1; }
            }
        }
    }
}

// ---------------- kernel: capacity scan (fast path) + g_cnt reset ----------------
__global__ void route_kernel() {
    int tid = threadIdx.x;
    bool over = false;
#pragma unroll
    for (int e = 0; e < 8; e++) over |= (g_cnt[e] > CAP);
    __syncthreads();
    if (tid < 8) g_cnt[tid] = 0;
    if (!over) return;

    int lane = tid & 31, warp = tid >> 5;
    int base = tid * 16;

    unsigned char le[16];
    int cnt[8] = {};
    for (int j = 0; j < 16; j++) {
        int a = base + j;
        int s = a >> 13, t = a & (T_TOK - 1);
        int e = g_exp[s][t];
        le[j] = (unsigned char)e;
        cnt[e]++;
    }
    __shared__ int warpsum[32][8];
    int excl[8];
#pragma unroll
    for (int e = 0; e < 8; e++) {
        int v = cnt[e], inc = v;
        for (int o = 1; o < 32; o <<= 1) {
            int nv = __shfl_up_sync(~0u, inc, o);
            if (lane >= o) inc += nv;
        }
        excl[e] = inc - v;
        if (lane == 31) warpsum[warp][e] = inc;
    }
    __syncthreads();
    if (warp == 0) {
#pragma unroll
        for (int e = 0; e < 8; e++) {
            int v = warpsum[lane][e], inc = v;
            for (int o = 1; o < 32; o <<= 1) {
                int nv = __shfl_up_sync(~0u, inc, o);
                if (lane >= o) inc += nv;
            }
            warpsum[lane][e] = inc - v;
        }
    }
    __syncthreads();
#pragma unroll
    for (int e = 0; e < 8; e++) excl[e] += warpsum[warp][e];

    for (int j = 0; j < 16; j++) {
        int a = base + j;
        int s = a >> 13, t = a & (T_TOK - 1);
        int e = le[j];
        int pos = excl[e]++;
        if (pos >= CAP) g_gate[s][t] = 0.f;
    }
}

// ---------------- fp16 2-term HMMA GEMM (128x256 CTA, 4x4 warps of 32x64) -------
#define GBM 128
#define GBN 256
#define GKC 64
#define NCHUNK 16
#define A_BYTES 32768                  // x_hi 128 rows + x_lo 128 rows, 128B each
#define B_BYTES 32768                  // W_hi 256 rows x 128B
#define STAGE_BYTES (A_BYTES + B_BYTES)   // 64 KB
#define NSTAGE 3
#define SMEM_REQ (NSTAGE * STAGE_BYTES)   // 192 KB, 1 CTA/SM, 16 warps
#define NTHR 512

__device__ __forceinline__ void issue_stage(unsigned sbase, int chunk, int mBase, int nBase,
                                            int tid) {
    int k0 = chunk * GKC;
#pragma unroll
    for (int q = 0; q < 4; q++) {                 // A: rows 0-127 x_hi, 128-255 x_lo
        int u = q * NTHR + tid;
        int row = u >> 3, ch = u & 7;
        const __half* ap = (q < 2) ? (g_xhi + (size_t)(mBase + row) * DMODEL)
                                   : (g_xlo + (size_t)(mBase + row - 128) * DMODEL);
        unsigned off = row * 128 + (((unsigned)(ch ^ (row & 7))) << 4);
        CP_ASYNC16(sbase + off, ap + k0 + ch * 8);
    }
#pragma unroll
    for (int q = 0; q < 4; q++) {                 // B: W fp16, 256 rows
        int u = q * NTHR + tid;
        int row = u >> 3, ch = u & 7;
        const __half* bp = g_w1t + (size_t)(nBase + row) * DMODEL;
        unsigned off = A_BYTES + row * 128 + (((unsigned)(ch ^ (row & 7))) << 4);
        CP_ASYNC16(sbase + off, bp + k0 + ch * 8);
    }
}

__global__ __launch_bounds__(NTHR, 1)
void ffn_tc_kernel(const float* __restrict__ B1, const float* __restrict__ A2) {
    extern __shared__ char dsm[];
    unsigned sbase = smem_u32(dsm);

    int tid = threadIdx.x, wid = tid >> 5, lane = tid & 31;
    int wm = wid & 3, wn = wid >> 2;
    int mBase = blockIdx.y * GBM, nBase = blockIdx.x * GBN;

    float acc[2][8][4] = {};

    issue_stage(sbase + 0 * STAGE_BYTES, 0, mBase, nBase, tid); CP_COMMIT();
    issue_stage(sbase + 1 * STAGE_BYTES, 1, mBase, nBase, tid); CP_COMMIT();

    int grp = lane >> 3, r8 = lane & 7;
    int a_m  = wm * 32 + (grp & 1) * 8 + r8;
    int a_ch = grp >> 1;
    int b_n  = wn * 64 + (grp >> 1) * 8 + r8;
    int b_ch = grp & 1;

    int stageIdx = 0;
    for (int c = 0; c < NCHUNK; c++) {
        if (c >= NCHUNK - 1) { CP_WAIT0(); } else { CP_WAIT1(); }
        __syncthreads();                 // buffer c ready; compute(c-1) done by all warps
        if (c + 2 < NCHUNK) {            // writes stage (c+2)%3 == (c-1)%3: safe
            int wIdx = stageIdx + 2; if (wIdx >= NSTAGE) wIdx -= NSTAGE;
            issue_stage(sbase + wIdx * STAGE_BYTES, c + 2, mBase, nBase, tid);
            CP_COMMIT();
        }
        unsigned st = sbase + stageIdx * STAGE_BYTES;
#pragma unroll
        for (int ks = 0; ks < 4; ks++) {
            unsigned ah[2][4], al[2][4];
#pragma unroll
            for (int mf = 0; mf < 2; mf++) {
                int m = a_m + mf * 16;
                int ch = 2 * ks + a_ch;
                unsigned sw = (((unsigned)(ch ^ (m & 7))) << 4);
                ldmx4(st + m * 128 + sw, ah[mf][0], ah[mf][1], ah[mf][2], ah[mf][3]);
                ldmx4(st + (m + 128) * 128 + sw, al[mf][0], al[mf][1], al[mf][2], al[mf][3]);
            }
            unsigned b[8][2];
#pragma unroll
            for (int nf2 = 0; nf2 < 4; nf2++) {
                int n = b_n + nf2 * 16;
                int ch = 2 * ks + b_ch;
                unsigned addr = st + A_BYTES + n * 128 + (((unsigned)(ch ^ (n & 7))) << 4);
                ldmx4(addr, b[nf2 * 2][0], b[nf2 * 2][1], b[nf2 * 2 + 1][0], b[nf2 * 2 + 1][1]);
            }
#pragma unroll
            for (int mf = 0; mf < 2; mf++)
#pragma unroll
                for (int nf = 0; nf < 8; nf++) {
                    mma16816h(acc[mf][nf], ah[mf], b[nf]);   // x_hi . W
                    mma16816h(acc[mf][nf], al[mf], b[nf]);   // x_lo . W
                }
        }
        if (++stageIdx == NSTAGE) stageIdx = 0;
    }
    __syncthreads();

    // ---- epilogue ----
    float* ep_w  = (float*)dsm;                       // [256][33]
    float* ep_w2 = (float*)(dsm + 33792);             // [256][2]
    float* ep_g  = (float*)(dsm + 35840);             // [2][128]
    float* ep_u  = (float*)(dsm + 36864);             // [2][128][2]
    int*   ep_e  = (int*)  (dsm + 38912);             // [2][128]

#pragma unroll
    for (int it = 0; it < 16; it++) {
        int idx = it * NTHR + tid;
        int n = idx >> 5, e = (idx >> 2) & 7, q = idx & 3;
        float v;
        if (q < 2) v = B1[(size_t)(e * 2 + q) * FFDIM + nBase + n];
        else       v = A2[(size_t)e * FFDIM * 2 + (size_t)(nBase + n) * 2 + (q - 2)];
        ep_w[n * 33 + e * 4 + q] = v;
    }
    ep_w2[tid] = g_w2wh[nBase * 2 + tid];
    if (tid < 256) {
        int s = tid >> 7, m = tid & 127;
        int t = mBase + m;
        ep_g[s * 128 + m] = g_gate[s][t];
        ep_e[s * 128 + m] = g_exp[s][t];
        ep_u[(s * 128 + m) * 2 + 0] = g_u1[s][t][0];
        ep_u[(s * 128 + m) * 2 + 1] = g_u1[s][t][1];
    }
    __syncthreads();

    const float GC  = 0.7978845608028654f;
    const float T2L = 2.8853900817779268f;
    int quad = lane >> 2, qi = lane & 3;

#pragma unroll
    for (int mf = 0; mf < 2; mf++) {
#pragma unroll
        for (int q8 = 0; q8 < 2; q8++) {
            int m = wm * 32 + mf * 16 + q8 * 8 + quad;
            int t = mBase + m;
#pragma unroll
            for (int s = 0; s < 2; s++) {
                float w = ep_g[s * 128 + m];
                float p0 = 0.f, p1 = 0.f, p2 = 0.f, p3 = 0.f;
                if (w != 0.f) {
                    int e = ep_e[s * 128 + m];
                    float u0 = ep_u[(s * 128 + m) * 2 + 0];
                    float u1 = ep_u[(s * 128 + m) * 2 + 1];
                    const float* wb = ep_w + e * 4;
#pragma unroll
                    for (int nf = 0; nf < 8; nf++) {
#pragma unroll
                        for (int r = 0; r < 2; r++) {
                            int n = wn * 64 + nf * 8 + 2 * qi + r;
                            float av = acc[mf][nf][q8 * 2 + r];
                            float b1r0 = wb[n * 33 + 0], b1r1 = wb[n * 33 + 1];
                            float v = av + u0 * b1r0 + u1 * b1r1;
                            float yy = GC * (v + 0.044715f * v * v * v);
                            float ex = exp2f(yy * T2L);
                            float th = 1.0f - __fdividef(2.0f, ex + 1.0f);
                            float h  = 0.5f * v * (1.0f + th);
                            p0 += h * ep_w2[n * 2];
                            p1 += h * ep_w2[n * 2 + 1];
                            p2 += h * wb[n * 33 + 2];
                            p3 += h * wb[n * 33 + 3];
                        }
                    }
                }
                for (int o = 1; o <= 2; o <<= 1) {
                    p0 += __shfl_xor_sync(~0u, p0, o);
                    p1 += __shfl_xor_sync(~0u, p1, o);
                    p2 += __shfl_xor_sync(~0u, p2, o);
                    p3 += __shfl_xor_sync(~0u, p3, o);
                }
                if (qi == 0 && w != 0.f) {
                    atomicAdd(&g_acc[t][s][0], p0);
                    atomicAdd(&g_acc[t][s][1], p1);
                    atomicAdd(&g_acc[t][s][2], p2);
                    atomicAdd(&g_acc[t][s][3], p3);
                }
            }
        }
    }
}

// ---------------- combine + pool: two-stage deterministic reduction ----------------
__global__ void final_part_kernel() {
    __shared__ float red[256][2];
    int part = blockIdx.x, b = blockIdx.y, tid = threadIdx.x;
    int t = b * SEQ + part * 256 + tid;
    float s0 = 0.f, s1 = 0.f;
#pragma unroll
    for (int s = 0; s < 2; s++) {
        float w = g_gate[s][t];
        if (w != 0.f) {
            int e = g_exp[s][t];
            float d0 = g_acc[t][s][0], d1 = g_acc[t][s][1];
            float a0 = g_acc[t][s][2], a1 = g_acc[t][s][3];
            float z0 = d0 + LSCALE * (a0 * g_b2wh[e * 4 + 0] + a1 * g_b2wh[e * 4 + 2]);
            float z1 = d1 + LSCALE * (a0 * g_b2wh[e * 4 + 1] + a1 * g_b2wh[e * 4 + 3]);
            s0 += w * z0; s1 += w * z1;
        }
    }
    red[tid][0] = s0; red[tid][1] = s1;
    __syncthreads();
    for (int o = 128; o; o >>= 1) {
        if (tid < o) { red[tid][0] += red[tid + o][0]; red[tid][1] += red[tid + o][1]; }
        __syncthreads();
    }
    if (tid == 0) { g_part[b][part][0] = red[0][0]; g_part[b][part][1] = red[0][1]; }
}

__global__ void final_sum_kernel(const float* __restrict__ bh, float* __restrict__ out) {
    int tid = threadIdx.x;
    if (tid < NBATCH * 2) {
        int b = tid >> 1, c = tid & 1;
        float s = 0.f;
#pragma unroll
        for (int p = 0; p < 8; p++) s += g_part[b][p][c];
        out[b * 2 + c] = s / (float)SEQ + bh[c];
    }
}

// ---------------- launch ----------------
extern "C" void kernel_launch(void* const* d_in, const int* in_sizes, int n_in,
                              void* d_out, int out_size) {
    const float* x  = (const float*)d_in[0];
    const float* Wg = (const float*)d_in[1];
    const float* W1 = (const float*)d_in[2];
    const float* W2 = (const float*)d_in[3];
    const float* A1 = (const float*)d_in[4];
    const float* B1 = (const float*)d_in[5];
    const float* A2 = (const float*)d_in[6];
    const float* B2 = (const float*)d_in[7];
    const float* Wh = (const float*)d_in[8];
    const float* bh = (const float*)d_in[9];

    cudaFuncSetAttribute(ffn_tc_kernel, cudaFuncAttributeMaxDynamicSharedMemorySize, SMEM_REQ);

    aux_kernel<<<GATE_BLOCKS + CONVW_BLOCKS + PREP_BLOCKS, 256>>>(x, Wg, A1, W1, W2, Wh, B2);
    route_kernel<<<1, 1024>>>();
    ffn_tc_kernel<<<dim3(FFDIM / GBN, T_TOK / GBM), NTHR, SMEM_REQ>>>(B1, A2);
    final_part_kernel<<<dim3(8, NBATCH), 256>>>();
    final_sum_kernel<<<1, 32>>>(bh, (float*)d_out);
}

// round 16
// speedup vs baseline: 1.9228x; 1.4206x over previous
#include <cuda_runtime.h>
#include <cuda_fp16.h>
#include <math.h>

// ---------------- problem constants ----------------
#define T_TOK 8192
#define DMODEL 1024
#define FFDIM 4096
#define NEXP 8
#define CAP 2560
#define SEQ 2048
#define NBATCH 4
#define LSCALE 2.0f

// ---------------- device scratch ----------------
__device__ float g_w2wh[FFDIM * 2];
__device__ float g_b2wh[NEXP * 2 * 2];
__device__ int   g_exp[2][T_TOK];
__device__ float g_gate[2][T_TOK];
__device__ float g_u1[2][T_TOK][2];
__device__ float g_acc[T_TOK][2][4];
__device__ int   g_cnt[NEXP];
__device__ float g_part[NBATCH][8][2];

__device__ __half g_xh[T_TOK * DMODEL];       // fp16 x
__device__ __half g_w1t[FFDIM * DMODEL];      // W1 transposed, fp16

// ---------------- PTX helpers ----------------
__device__ __forceinline__ unsigned smem_u32(const void* p) {
    unsigned a;
    asm("{ .reg .u64 t; cvta.to.shared.u64 t, %1; cvt.u32.u64 %0, t; }" : "=r"(a) : "l"(p));
    return a;
}
#define CP_ASYNC16(saddr, gptr) \
    asm volatile("cp.async.cg.shared.global [%0], [%1], 16;" :: "r"(saddr), "l"(gptr))
#define CP_COMMIT() asm volatile("cp.async.commit_group;" ::: "memory")
#define CP_WAIT1()  asm volatile("cp.async.wait_group 1;" ::: "memory")
#define CP_WAIT0()  asm volatile("cp.async.wait_group 0;" ::: "memory")

__device__ __forceinline__ void ldmx4(unsigned addr, unsigned& r0, unsigned& r1,
                                      unsigned& r2, unsigned& r3) {
    asm volatile("ldmatrix.sync.aligned.m8n8.x4.shared.b16 {%0,%1,%2,%3}, [%4];"
                 : "=r"(r0), "=r"(r1), "=r"(r2), "=r"(r3) : "r"(addr));
}
__device__ __forceinline__ void mma16816h(float* c, const unsigned* a, const unsigned* b) {
    asm volatile("mma.sync.aligned.m16n8k16.row.col.f32.f16.f16.f32 "
                 "{%0,%1,%2,%3}, {%4,%5,%6,%7}, {%8,%9}, {%0,%1,%2,%3};"
                 : "+f"(c[0]), "+f"(c[1]), "+f"(c[2]), "+f"(c[3])
                 : "r"(a[0]), "r"(a[1]), "r"(a[2]), "r"(a[3]), "r"(b[0]), "r"(b[1]));
}

// ---------------- merged aux kernel: gate | convert_w | prep ----------------
#define GATE_BLOCKS 1024
#define CONVW_BLOCKS 4096
#define PREP_BLOCKS 513

__global__ void aux_kernel(const float* __restrict__ x,  const float* __restrict__ Wg,
                           const float* __restrict__ A1, const float* __restrict__ W1,
                           const float* __restrict__ W2, const float* __restrict__ Wh,
                           const float* __restrict__ B2) {
    __shared__ float sbuf[NEXP * DMODEL];     // 32 KB, reused per role
    int bid = blockIdx.x, tid = threadIdx.x;

    if (bid < GATE_BLOCKS) {
        // ---- gating + u1 + x fp16 conversion + hist + zero accum ----
        float (*wgt)[DMODEL] = (float(*)[DMODEL])sbuf;
        for (int i = tid; i < DMODEL * NEXP; i += 256) {
            int d = i >> 3, e = i & 7;
            wgt[e][d] = Wg[i];
        }
        __syncthreads();

        int warp = tid >> 5, lane = tid & 31;
        int t = bid * 8 + warp;
        const float* xr = x + (size_t)t * DMODEL;

        float4 xv[8];
#pragma unroll
        for (int i = 0; i < 8; i++) xv[i] = *(const float4*)(xr + i * 128 + lane * 4);

#pragma unroll
        for (int i = 0; i < 8; i++) {
            int d = i * 128 + lane * 4;
            __half2 h01 = __floats2half2_rn(xv[i].x, xv[i].y);
            __half2 h23 = __floats2half2_rn(xv[i].z, xv[i].w);
            uint2 hv;
            hv.x = *(unsigned*)&h01; hv.y = *(unsigned*)&h23;
            *(uint2*)(g_xh + (size_t)t * DMODEL + d) = hv;
        }

        float lg[8] = {};
#pragma unroll
        for (int e = 0; e < 8; e++) {
#pragma unroll
            for (int i = 0; i < 8; i++) {
                float4 wv = *(const float4*)&wgt[e][i * 128 + lane * 4];
                lg[e] += xv[i].x * wv.x + xv[i].y * wv.y + xv[i].z * wv.z + xv[i].w * wv.w;
            }
        }
#pragma unroll
        for (int e = 0; e < 8; e++)
            for (int o = 16; o; o >>= 1) lg[e] += __shfl_xor_sync(~0u, lg[e], o);

        float v0 = -1e30f, v1 = -1e30f; int e0 = 0, e1 = 0;
#pragma unroll
        for (int e = 0; e < 8; e++) {
            float l = lg[e];
            if (l > v0)      { v1 = v0; e1 = e0; v0 = l; e0 = e; }
            else if (l > v1) { v1 = l;  e1 = e; }
        }
        float q  = expf(v1 - v0);
        float g0 = 1.0f / (1.0f + q);
        float g1 = q * g0;

        float u00 = 0.f, u01 = 0.f, u10 = 0.f, u11 = 0.f;
        const float* a1e0 = A1 + (size_t)e0 * DMODEL * 2;
        const float* a1e1 = A1 + (size_t)e1 * DMODEL * 2;
#pragma unroll
        for (int i = 0; i < 8; i++) {
            int base = 2 * (i * 128 + lane * 4);
            float4 p0 = *(const float4*)(a1e0 + base);
            float4 p1 = *(const float4*)(a1e0 + base + 4);
            u00 += xv[i].x * p0.x + xv[i].y * p0.z + xv[i].z * p1.x + xv[i].w * p1.z;
            u01 += xv[i].x * p0.y + xv[i].y * p0.w + xv[i].z * p1.y + xv[i].w * p1.w;
            float4 q0 = *(const float4*)(a1e1 + base);
            float4 q1 = *(const float4*)(a1e1 + base + 4);
            u10 += xv[i].x * q0.x + xv[i].y * q0.z + xv[i].z * q1.x + xv[i].w * q1.z;
            u11 += xv[i].x * q0.y + xv[i].y * q0.w + xv[i].z * q1.y + xv[i].w * q1.w;
        }
        for (int o = 16; o; o >>= 1) {
            u00 += __shfl_xor_sync(~0u, u00, o); u01 += __shfl_xor_sync(~0u, u01, o);
            u10 += __shfl_xor_sync(~0u, u10, o); u11 += __shfl_xor_sync(~0u, u11, o);
        }
        if (lane == 0) {
            g_exp[0][t] = e0;  g_exp[1][t] = e1;
            g_gate[0][t] = g0; g_gate[1][t] = g1;
            g_u1[0][t][0] = LSCALE * u00; g_u1[0][t][1] = LSCALE * u01;
            g_u1[1][t][0] = LSCALE * u10; g_u1[1][t][1] = LSCALE * u11;
            atomicAdd(&g_cnt[e0], 1);
            atomicAdd(&g_cnt[e1], 1);
        }
        if (lane < 8) (&g_acc[t][0][0])[lane] = 0.f;
    } else if (bid < GATE_BLOCKS + CONVW_BLOCKS) {
        // ---- W1 -> transposed fp16 (single copy, 4-byte stores) ----
        float (*tile)[33] = (float(*)[33])sbuf;
        int idx = bid - GATE_BLOCKS;
        int bx = idx & 127, by = idx >> 7;
        int tx = tid & 31, ty = tid >> 5;
#pragma unroll
        for (int i = 0; i < 4; i++) {
            int k = by * 32 + ty + i * 8, n = bx * 32 + tx;
            tile[ty + i * 8][tx] = W1[(size_t)k * FFDIM + n];
        }
        __syncthreads();
#pragma unroll
        for (int i = 0; i < 2; i++) {
            int u = i * 256 + tid;
            int nl = u >> 4, kp = u & 15;
            int n = bx * 32 + nl;
            int k = by * 32 + kp * 2;
            __half2 hv = __floats2half2_rn(tile[kp * 2][nl], tile[kp * 2 + 1][nl]);
            *(__half2*)(g_w1t + (size_t)n * DMODEL + k) = hv;
        }
    } else {
        // ---- prep: head-folded matrices ----
        int pb = bid - GATE_BLOCKS - CONVW_BLOCKS;
        int gw = pb * 8 + (tid >> 5);
        int lane = tid & 31;
        if (gw < FFDIM) {
            const float* wr = W2 + (size_t)gw * DMODEL;
            float s0 = 0.f, s1 = 0.f;
            for (int d = lane; d < DMODEL; d += 32) {
                float wv = wr[d];
                s0 += wv * Wh[2 * d]; s1 += wv * Wh[2 * d + 1];
            }
            for (int o = 16; o; o >>= 1) {
                s0 += __shfl_xor_sync(~0u, s0, o); s1 += __shfl_xor_sync(~0u, s1, o);
            }
            if (lane == 0) { g_w2wh[2 * gw] = s0; g_w2wh[2 * gw + 1] = s1; }
        } else {
            int w = gw - FFDIM;
            for (int p = 2 * w; p < 2 * w + 2 && p < 16; p++) {
                const float* br = B2 + (size_t)p * DMODEL;
                float s0 = 0.f, s1 = 0.f;
                for (int d = lane; d < DMODEL; d += 32) {
                    float bv = br[d];
                    s0 += bv * Wh[2 * d]; s1 += bv * Wh[2 * d + 1];
                }
                for (int o = 16; o; o >>= 1) {
                    s0 += __shfl_xor_sync(~0u, s0, o); s1 += __shfl_xor_sync(~0u, s1, o);
                }
                if (lane == 0) { g_b2wh[2 * p] = s0; g_b2wh[2 * p + 1] = s1; }
            }
        }
    }
}

// ---------------- kernel: capacity scan (fast path) + g_cnt reset ----------------
__global__ void route_kernel() {
    int tid = threadIdx.x;
    bool over = false;
#pragma unroll
    for (int e = 0; e < 8; e++) over |= (g_cnt[e] > CAP);
    __syncthreads();
    if (tid < 8) g_cnt[tid] = 0;
    if (!over) return;

    int lane = tid & 31, warp = tid >> 5;
    int base = tid * 16;

    unsigned char le[16];
    int cnt[8] = {};
    for (int j = 0; j < 16; j++) {
        int a = base + j;
        int s = a >> 13, t = a & (T_TOK - 1);
        int e = g_exp[s][t];
        le[j] = (unsigned char)e;
        cnt[e]++;
    }
    __shared__ int warpsum[32][8];
    int excl[8];
#pragma unroll
    for (int e = 0; e < 8; e++) {
        int v = cnt[e], inc = v;
        for (int o = 1; o < 32; o <<= 1) {
            int nv = __shfl_up_sync(~0u, inc, o);
            if (lane >= o) inc += nv;
        }
        excl[e] = inc - v;
        if (lane == 31) warpsum[warp][e] = inc;
    }
    __syncthreads();
    if (warp == 0) {
#pragma unroll
        for (int e = 0; e < 8; e++) {
            int v = warpsum[lane][e], inc = v;
            for (int o = 1; o < 32; o <<= 1) {
                int nv = __shfl_up_sync(~0u, inc, o);
                if (lane >= o) inc += nv;
            }
            warpsum[lane][e] = inc - v;
        }
    }
    __syncthreads();
#pragma unroll
    for (int e = 0; e < 8; e++) excl[e] += warpsum[warp][e];

    for (int j = 0; j < 16; j++) {
        int a = base + j;
        int s = a >> 13, t = a & (T_TOK - 1);
        int e = le[j];
        int pos = excl[e]++;
        if (pos >= CAP) g_gate[s][t] = 0.f;
    }
}

// ---------------- single-term fp16 HMMA GEMM (128x256 CTA, 4x4 warps of 32x64) ----
#define GBM 128
#define GBN 256
#define GKC 64
#define NCHUNK 16
#define A_BYTES 16384                  // x 128 rows x 128B
#define B_BYTES 32768                  // W 256 rows x 128B
#define STAGE_BYTES (A_BYTES + B_BYTES)   // 48 KB
#define NSTAGE 3
#define SMEM_REQ (NSTAGE * STAGE_BYTES)   // 144 KB
#define NTHR 512

__device__ __forceinline__ void issue_stage(unsigned sbase, int chunk, int mBase, int nBase,
                                            int tid) {
    int k0 = chunk * GKC;
#pragma unroll
    for (int q = 0; q < 2; q++) {                 // A: 128 rows x 8 ch = 1024
        int u = q * NTHR + tid;
        int row = u >> 3, ch = u & 7;
        const __half* ap = g_xh + (size_t)(mBase + row) * DMODEL;
        unsigned off = row * 128 + (((unsigned)(ch ^ (row & 7))) << 4);
        CP_ASYNC16(sbase + off, ap + k0 + ch * 8);
    }
#pragma unroll
    for (int q = 0; q < 4; q++) {                 // B: 256 rows x 8 ch = 2048
        int u = q * NTHR + tid;
        int row = u >> 3, ch = u & 7;
        const __half* bp = g_w1t + (size_t)(nBase + row) * DMODEL;
        unsigned off = A_BYTES + row * 128 + (((unsigned)(ch ^ (row & 7))) << 4);
        CP_ASYNC16(sbase + off, bp + k0 + ch * 8);
    }
}

__global__ __launch_bounds__(NTHR, 1)
void ffn_tc_kernel(const float* __restrict__ B1, const float* __restrict__ A2) {
    extern __shared__ char dsm[];
    unsigned sbase = smem_u32(dsm);

    int tid = threadIdx.x, wid = tid >> 5, lane = tid & 31;
    int wm = wid & 3, wn = wid >> 2;
    int mBase = blockIdx.y * GBM, nBase = blockIdx.x * GBN;

    float acc[2][8][4] = {};

    issue_stage(sbase + 0 * STAGE_BYTES, 0, mBase, nBase, tid); CP_COMMIT();
    issue_stage(sbase + 1 * STAGE_BYTES, 1, mBase, nBase, tid); CP_COMMIT();

    int grp = lane >> 3, r8 = lane & 7;
    int a_m  = wm * 32 + (grp & 1) * 8 + r8;
    int a_ch = grp >> 1;
    int b_n  = wn * 64 + (grp >> 1) * 8 + r8;
    int b_ch = grp & 1;

    int stageIdx = 0;
    for (int c = 0; c < NCHUNK; c++) {
        if (c >= NCHUNK - 1) { CP_WAIT0(); } else { CP_WAIT1(); }
        __syncthreads();
        if (c + 2 < NCHUNK) {
            int wIdx = stageIdx + 2; if (wIdx >= NSTAGE) wIdx -= NSTAGE;
            issue_stage(sbase + wIdx * STAGE_BYTES, c + 2, mBase, nBase, tid);
            CP_COMMIT();
        }
        unsigned st = sbase + stageIdx * STAGE_BYTES;
#pragma unroll
        for (int ks = 0; ks < 4; ks++) {
            unsigned a[2][4];
#pragma unroll
            for (int mf = 0; mf < 2; mf++) {
                int m = a_m + mf * 16;
                int ch = 2 * ks + a_ch;
                unsigned sw = (((unsigned)(ch ^ (m & 7))) << 4);
                ldmx4(st + m * 128 + sw, a[mf][0], a[mf][1], a[mf][2], a[mf][3]);
            }
            unsigned b[8][2];
#pragma unroll
            for (int nf2 = 0; nf2 < 4; nf2++) {
                int n = b_n + nf2 * 16;
                int ch = 2 * ks + b_ch;
                unsigned addr = st + A_BYTES + n * 128 + (((unsigned)(ch ^ (n & 7))) << 4);
                ldmx4(addr, b[nf2 * 2][0], b[nf2 * 2][1], b[nf2 * 2 + 1][0], b[nf2 * 2 + 1][1]);
            }
#pragma unroll
            for (int mf = 0; mf < 2; mf++)
#pragma unroll
                for (int nf = 0; nf < 8; nf++)
                    mma16816h(acc[mf][nf], a[mf], b[nf]);
        }
        if (++stageIdx == NSTAGE) stageIdx = 0;
    }
    __syncthreads();

    // ---- epilogue ----
    float* ep_w  = (float*)dsm;                       // [256][33]
    float* ep_w2 = (float*)(dsm + 33792);             // [256][2]
    float* ep_g  = (float*)(dsm + 35840);             // [2][128]
    float* ep_u  = (float*)(dsm + 36864);             // [2][128][2]
    int*   ep_e  = (int*)  (dsm + 38912);             // [2][128]

#pragma unroll
    for (int it = 0; it < 16; it++) {
        int idx = it * NTHR + tid;
        int n = idx >> 5, e = (idx >> 2) & 7, q = idx & 3;
        float v;
        if (q < 2) v = B1[(size_t)(e * 2 + q) * FFDIM + nBase + n];
        else       v = A2[(size_t)e * FFDIM * 2 + (size_t)(nBase + n) * 2 + (q - 2)];
        ep_w[n * 33 + e * 4 + q] = v;
    }
    ep_w2[tid] = g_w2wh[nBase * 2 + tid];
    if (tid < 256) {
        int s = tid >> 7, m = tid & 127;
        int t = mBase + m;
        ep_g[s * 128 + m] = g_gate[s][t];
        ep_e[s * 128 + m] = g_exp[s][t];
        ep_u[(s * 128 + m) * 2 + 0] = g_u1[s][t][0];
        ep_u[(s * 128 + m) * 2 + 1] = g_u1[s][t][1];
    }
    __syncthreads();

    const float GC  = 0.7978845608028654f;
    const float T2L = 2.8853900817779268f;
    int quad = lane >> 2, qi = lane & 3;

#pragma unroll
    for (int mf = 0; mf < 2; mf++) {
#pragma unroll
        for (int q8 = 0; q8 < 2; q8++) {
            int m = wm * 32 + mf * 16 + q8 * 8 + quad;
            int t = mBase + m;
#pragma unroll
            for (int s = 0; s < 2; s++) {
                float w = ep_g[s * 128 + m];
                float p0 = 0.f, p1 = 0.f, p2 = 0.f, p3 = 0.f;
                if (w != 0.f) {
                    int e = ep_e[s * 128 + m];
                    float u0 = ep_u[(s * 128 + m) * 2 + 0];
                    float u1 = ep_u[(s * 128 + m) * 2 + 1];
                    const float* wb = ep_w + e * 4;
#pragma unroll
                    for (int nf = 0; nf < 8; nf++) {
#pragma unroll
                        for (int r = 0; r < 2; r++) {
                            int n = wn * 64 + nf * 8 + 2 * qi + r;
                            float av = acc[mf][nf][q8 * 2 + r];
                            float b1r0 = wb[n * 33 + 0], b1r1 = wb[n * 33 + 1];
                            float v = av + u0 * b1r0 + u1 * b1r1;
                            float yy = GC * (v + 0.044715f * v * v * v);
                            float ex = exp2f(yy * T2L);
                            float th = 1.0f - __fdividef(2.0f, ex + 1.0f);
                            float h  = 0.5f * v * (1.0f + th);
                            p0 += h * ep_w2[n * 2];
                            p1 += h * ep_w2[n * 2 + 1];
                            p2 += h * wb[n * 33 + 2];
                            p3 += h * wb[n * 33 + 3];
                        }
                    }
                }
                for (int o = 1; o <= 2; o <<= 1) {
                    p0 += __shfl_xor_sync(~0u, p0, o);
                    p1 += __shfl_xor_sync(~0u, p1, o);
                    p2 += __shfl_xor_sync(~0u, p2, o);
                    p3 += __shfl_xor_sync(~0u, p3, o);
                }
                if (qi == 0 && w != 0.f) {
                    atomicAdd(&g_acc[t][s][0], p0);
                    atomicAdd(&g_acc[t][s][1], p1);
                    atomicAdd(&g_acc[t][s][2], p2);
                    atomicAdd(&g_acc[t][s][3], p3);
                }
            }
        }
    }
}

// ---------------- combine + pool: two-stage deterministic reduction ----------------
__global__ void final_part_kernel() {
    __shared__ float red[256][2];
    int part = blockIdx.x, b = blockIdx.y, tid = threadIdx.x;
    int t = b * SEQ + part * 256 + tid;
    float s0 = 0.f, s1 = 0.f;
#pragma unroll
    for (int s = 0; s < 2; s++) {
        float w = g_gate[s][t];
        if (w != 0.f) {
            int e = g_exp[s][t];
            float d0 = g_acc[t][s][0], d1 = g_acc[t][s][1];
            float a0 = g_acc[t][s][2], a1 = g_acc[t][s][3];
            float z0 = d0 + LSCALE * (a0 * g_b2wh[e * 4 + 0] + a1 * g_b2wh[e * 4 + 2]);
            float z1 = d1 + LSCALE * (a0 * g_b2wh[e * 4 + 1] + a1 * g_b2wh[e * 4 + 3]);
            s0 += w * z0; s1 += w * z1;
        }
    }
    red[tid][0] = s0; red[tid][1] = s1;
    __syncthreads();
    for (int o = 128; o; o >>= 1) {
        if (tid < o) { red[tid][0] += red[tid + o][0]; red[tid][1] += red[tid + o][1]; }
        __syncthreads();
    }
    if (tid == 0) { g_part[b][part][0] = red[0][0]; g_part[b][part][1] = red[0][1]; }
}

__global__ void final_sum_kernel(const float* __restrict__ bh, float* __restrict__ out) {
    int tid = threadIdx.x;
    if (tid < NBATCH * 2) {
        int b = tid >> 1, c = tid & 1;
        float s = 0.f;
#pragma unroll
        for (int p = 0; p < 8; p++) s += g_part[b][p][c];
        out[b * 2 + c] = s / (float)SEQ + bh[c];
    }
}

// ---------------- launch ----------------
extern "C" void kernel_launch(void* const* d_in, const int* in_sizes, int n_in,
                              void* d_out, int out_size) {
    const float* x  = (const float*)d_in[0];
    const float* Wg = (const float*)d_in[1];
    const float* W1 = (const float*)d_in[2];
    const float* W2 = (const float*)d_in[3];
    const float* A1 = (const float*)d_in[4];
    const float* B1 = (const float*)d_in[5];
    const float* A2 = (const float*)d_in[6];
    const float* B2 = (const float*)d_in[7];
    const float* Wh = (const float*)d_in[8];
    const float* bh = (const float*)d_in[9];

    cudaFuncSetAttribute(ffn_tc_kernel, cudaFuncAttributeMaxDynamicSharedMemorySize, SMEM_REQ);

    aux_kernel<<<GATE_BLOCKS + CONVW_BLOCKS + PREP_BLOCKS, 256>>>(x, Wg, A1, W1, W2, Wh, B2);
    route_kernel<<<1, 1024>>>();
    ffn_tc_kernel<<<dim3(FFDIM / GBN, T_TOK / GBM), NTHR, SMEM_REQ>>>(B1, A2);
    final_part_kernel<<<dim3(8, NBATCH), 256>>>();
    final_sum_kernel<<<1, 32>>>(bh, (float*)d_out);
}

// round 17
// speedup vs baseline: 1.9327x; 1.0051x over previous
#include <cuda_runtime.h>
#include <cuda_fp16.h>
#include <math.h>

// ---------------- problem constants ----------------
#define T_TOK 8192
#define DMODEL 1024
#define FFDIM 4096
#define NEXP 8
#define CAP 2560
#define SEQ 2048
#define NBATCH 4
#define LSCALE 2.0f

// ---------------- device scratch ----------------
__device__ float g_w2wh[FFDIM * 2];
__device__ float g_b2wh[NEXP * 2 * 2];
__device__ int   g_exp[2][T_TOK];
__device__ float g_gate[2][T_TOK];
__device__ float g_u1[2][T_TOK][2];
__device__ float g_acc[T_TOK][2][4];
__device__ int   g_cnt[NEXP];
__device__ float g_part[NBATCH][8][2];
__device__ unsigned g_done;                    // final_part completion counter (self-reset)

__device__ __half g_xh[T_TOK * DMODEL];        // fp16 x
__device__ __half g_w1t[FFDIM * DMODEL];       // W1 transposed, fp16

// ---------------- PTX helpers ----------------
__device__ __forceinline__ unsigned smem_u32(const void* p) {
    unsigned a;
    asm("{ .reg .u64 t; cvta.to.shared.u64 t, %1; cvt.u32.u64 %0, t; }" : "=r"(a) : "l"(p));
    return a;
}
#define CP_ASYNC16(saddr, gptr) \
    asm volatile("cp.async.cg.shared.global [%0], [%1], 16;" :: "r"(saddr), "l"(gptr))
#define CP_COMMIT() asm volatile("cp.async.commit_group;" ::: "memory")
#define CP_WAIT1()  asm volatile("cp.async.wait_group 1;" ::: "memory")
#define CP_WAIT0()  asm volatile("cp.async.wait_group 0;" ::: "memory")

__device__ __forceinline__ void ldmx4(unsigned addr, unsigned& r0, unsigned& r1,
                                      unsigned& r2, unsigned& r3) {
    asm volatile("ldmatrix.sync.aligned.m8n8.x4.shared.b16 {%0,%1,%2,%3}, [%4];"
                 : "=r"(r0), "=r"(r1), "=r"(r2), "=r"(r3) : "r"(addr));
}
__device__ __forceinline__ void mma16816h(float* c, const unsigned* a, const unsigned* b) {
    asm volatile("mma.sync.aligned.m16n8k16.row.col.f32.f16.f16.f32 "
                 "{%0,%1,%2,%3}, {%4,%5,%6,%7}, {%8,%9}, {%0,%1,%2,%3};"
                 : "+f"(c[0]), "+f"(c[1]), "+f"(c[2]), "+f"(c[3])
                 : "r"(a[0]), "r"(a[1]), "r"(a[2]), "r"(a[3]), "r"(b[0]), "r"(b[1]));
}

// ---------------- merged aux kernel: gate | convert_w | prep ----------------
#define GATE_BLOCKS 1024
#define CONVW_BLOCKS 1024              // 64x64 tiles: (4096/64) x (1024/64)
#define PREP_BLOCKS 513

__global__ void aux_kernel(const float* __restrict__ x,  const float* __restrict__ Wg,
                           const float* __restrict__ A1, const float* __restrict__ W1,
                           const float* __restrict__ W2, const float* __restrict__ Wh,
                           const float* __restrict__ B2) {
    __shared__ float sbuf[NEXP * DMODEL];     // 32 KB, reused per role
    int bid = blockIdx.x, tid = threadIdx.x;

    if (bid < GATE_BLOCKS) {
        // ---- gating + u1 + x fp16 conversion + hist + zero accum ----
        float (*wgt)[DMODEL] = (float(*)[DMODEL])sbuf;
        for (int i = tid; i < DMODEL * NEXP; i += 256) {
            int d = i >> 3, e = i & 7;
            wgt[e][d] = Wg[i];
        }
        __syncthreads();

        int warp = tid >> 5, lane = tid & 31;
        int t = bid * 8 + warp;
        const float* xr = x + (size_t)t * DMODEL;

        float4 xv[8];
#pragma unroll
        for (int i = 0; i < 8; i++) xv[i] = *(const float4*)(xr + i * 128 + lane * 4);

#pragma unroll
        for (int i = 0; i < 8; i++) {
            int d = i * 128 + lane * 4;
            __half2 h01 = __floats2half2_rn(xv[i].x, xv[i].y);
            __half2 h23 = __floats2half2_rn(xv[i].z, xv[i].w);
            uint2 hv;
            hv.x = *(unsigned*)&h01; hv.y = *(unsigned*)&h23;
            *(uint2*)(g_xh + (size_t)t * DMODEL + d) = hv;
        }

        float lg[8] = {};
#pragma unroll
        for (int e = 0; e < 8; e++) {
#pragma unroll
            for (int i = 0; i < 8; i++) {
                float4 wv = *(const float4*)&wgt[e][i * 128 + lane * 4];
                lg[e] += xv[i].x * wv.x + xv[i].y * wv.y + xv[i].z * wv.z + xv[i].w * wv.w;
            }
        }
#pragma unroll
        for (int e = 0; e < 8; e++)
            for (int o = 16; o; o >>= 1) lg[e] += __shfl_xor_sync(~0u, lg[e], o);

        float v0 = -1e30f, v1 = -1e30f; int e0 = 0, e1 = 0;
#pragma unroll
        for (int e = 0; e < 8; e++) {
            float l = lg[e];
            if (l > v0)      { v1 = v0; e1 = e0; v0 = l; e0 = e; }
            else if (l > v1) { v1 = l;  e1 = e; }
        }
        float q  = expf(v1 - v0);
        float g0 = 1.0f / (1.0f + q);
        float g1 = q * g0;

        float u00 = 0.f, u01 = 0.f, u10 = 0.f, u11 = 0.f;
        const float* a1e0 = A1 + (size_t)e0 * DMODEL * 2;
        const float* a1e1 = A1 + (size_t)e1 * DMODEL * 2;
#pragma unroll
        for (int i = 0; i < 8; i++) {
            int base = 2 * (i * 128 + lane * 4);
            float4 p0 = *(const float4*)(a1e0 + base);
            float4 p1 = *(const float4*)(a1e0 + base + 4);
            u00 += xv[i].x * p0.x + xv[i].y * p0.z + xv[i].z * p1.x + xv[i].w * p1.z;
            u01 += xv[i].x * p0.y + xv[i].y * p0.w + xv[i].z * p1.y + xv[i].w * p1.w;
            float4 q0 = *(const float4*)(a1e1 + base);
            float4 q1 = *(const float4*)(a1e1 + base + 4);
            u10 += xv[i].x * q0.x + xv[i].y * q0.z + xv[i].z * q1.x + xv[i].w * q1.z;
            u11 += xv[i].x * q0.y + xv[i].y * q0.w + xv[i].z * q1.y + xv[i].w * q1.w;
        }
        for (int o = 16; o; o >>= 1) {
            u00 += __shfl_xor_sync(~0u, u00, o); u01 += __shfl_xor_sync(~0u, u01, o);
            u10 += __shfl_xor_sync(~0u, u10, o); u11 += __shfl_xor_sync(~0u, u11, o);
        }
        if (lane == 0) {
            g_exp[0][t] = e0;  g_exp[1][t] = e1;
            g_gate[0][t] = g0; g_gate[1][t] = g1;
            g_u1[0][t][0] = LSCALE * u00; g_u1[0][t][1] = LSCALE * u01;
            g_u1[1][t][0] = LSCALE * u10; g_u1[1][t][1] = LSCALE * u11;
            atomicAdd(&g_cnt[e0], 1);
            atomicAdd(&g_cnt[e1], 1);
        }
        if (lane < 8) (&g_acc[t][0][0])[lane] = 0.f;
    } else if (bid < GATE_BLOCKS + CONVW_BLOCKS) {
        // ---- W1 -> transposed fp16, 64x64 tiles, float4 loads / uint2 stores ----
        float (*tile)[65] = (float(*)[65])sbuf;   // [64][65] = 16.3 KB
        int idx = bid - GATE_BLOCKS;
        int bx = idx & 63, by = idx >> 6;         // bx: n-tile (64 of 64), by: k-tile (16 of 64)
#pragma unroll
        for (int i = 0; i < 4; i++) {
            int u = i * 256 + tid;                // 1024 float4 units = 64 rows x 16 groups
            int k = u >> 4, cg = u & 15;
            float4 v = *(const float4*)(W1 + (size_t)(by * 64 + k) * FFDIM + bx * 64 + cg * 4);
            tile[k][cg * 4 + 0] = v.x; tile[k][cg * 4 + 1] = v.y;
            tile[k][cg * 4 + 2] = v.z; tile[k][cg * 4 + 3] = v.w;
        }
        __syncthreads();
#pragma unroll
        for (int i = 0; i < 4; i++) {
            int u = i * 256 + tid;                // 1024 units = 64 n x 16 k-quads
            int nl = u >> 4, kq = u & 15;
            int k = kq * 4;
            __half2 h01 = __floats2half2_rn(tile[k + 0][nl], tile[k + 1][nl]);
            __half2 h23 = __floats2half2_rn(tile[k + 2][nl], tile[k + 3][nl]);
            uint2 hv;
            hv.x = *(unsigned*)&h01; hv.y = *(unsigned*)&h23;
            *(uint2*)(g_w1t + (size_t)(bx * 64 + nl) * DMODEL + by * 64 + k) = hv;
        }
    } else {
        // ---- prep: head-folded matrices ----
        int pb = bid - GATE_BLOCKS - CONVW_BLOCKS;
        int gw = pb * 8 + (tid >> 5);
        int lane = tid & 31;
        if (gw < FFDIM) {
            const float* wr = W2 + (size_t)gw * DMODEL;
            float s0 = 0.f, s1 = 0.f;
            for (int d = lane; d < DMODEL; d += 32) {
                float wv = wr[d];
                s0 += wv * Wh[2 * d]; s1 += wv * Wh[2 * d + 1];
            }
            for (int o = 16; o; o >>= 1) {
                s0 += __shfl_xor_sync(~0u, s0, o); s1 += __shfl_xor_sync(~0u, s1, o);
            }
            if (lane == 0) { g_w2wh[2 * gw] = s0; g_w2wh[2 * gw + 1] = s1; }
        } else {
            int w = gw - FFDIM;
            for (int p = 2 * w; p < 2 * w + 2 && p < 16; p++) {
                const float* br = B2 + (size_t)p * DMODEL;
                float s0 = 0.f, s1 = 0.f;
                for (int d = lane; d < DMODEL; d += 32) {
                    float bv = br[d];
                    s0 += bv * Wh[2 * d]; s1 += bv * Wh[2 * d + 1];
                }
                for (int o = 16; o; o >>= 1) {
                    s0 += __shfl_xor_sync(~0u, s0, o); s1 += __shfl_xor_sync(~0u, s1, o);
                }
                if (lane == 0) { g_b2wh[2 * p] = s0; g_b2wh[2 * p + 1] = s1; }
            }
        }
    }
}

// ---------------- kernel: capacity scan (fast path) + g_cnt reset ----------------
__global__ void route_kernel() {
    int tid = threadIdx.x;
    bool over = false;
#pragma unroll
    for (int e = 0; e < 8; e++) over |= (g_cnt[e] > CAP);
    __syncthreads();
    if (tid < 8) g_cnt[tid] = 0;
    if (!over) return;

    int lane = tid & 31, warp = tid >> 5;
    int base = tid * 16;

    unsigned char le[16];
    int cnt[8] = {};
    for (int j = 0; j < 16; j++) {
        int a = base + j;
        int s = a >> 13, t = a & (T_TOK - 1);
        int e = g_exp[s][t];
        le[j] = (unsigned char)e;
        cnt[e]++;
    }
    __shared__ int warpsum[32][8];
    int excl[8];
#pragma unroll
    for (int e = 0; e < 8; e++) {
        int v = cnt[e], inc = v;
        for (int o = 1; o < 32; o <<= 1) {
            int nv = __shfl_up_sync(~0u, inc, o);
            if (lane >= o) inc += nv;
        }
        excl[e] = inc - v;
        if (lane == 31) warpsum[warp][e] = inc;
    }
    __syncthreads();
    if (warp == 0) {
#pragma unroll
        for (int e = 0; e < 8; e++) {
            int v = warpsum[lane][e], inc = v;
            for (int o = 1; o < 32; o <<= 1) {
                int nv = __shfl_up_sync(~0u, inc, o);
                if (lane >= o) inc += nv;
            }
            warpsum[lane][e] = inc - v;
        }
    }
    __syncthreads();
#pragma unroll
    for (int e = 0; e < 8; e++) excl[e] += warpsum[warp][e];

    for (int j = 0; j < 16; j++) {
        int a = base + j;
        int s = a >> 13, t = a & (T_TOK - 1);
        int e = le[j];
        int pos = excl[e]++;
        if (pos >= CAP) g_gate[s][t] = 0.f;
    }
}

// ---------------- single-term fp16 HMMA GEMM (128x256 CTA, 4x4 warps of 32x64) ----
#define GBM 128
#define GBN 256
#define GKC 64
#define NCHUNK 16
#define A_BYTES 16384
#define B_BYTES 32768
#define STAGE_BYTES (A_BYTES + B_BYTES)   // 48 KB
#define NSTAGE 3
#define SMEM_REQ (NSTAGE * STAGE_BYTES)   // 144 KB
#define NTHR 512

__device__ __forceinline__ void issue_stage(unsigned sbase, int chunk, int mBase, int nBase,
                                            int tid) {
    int k0 = chunk * GKC;
#pragma unroll
    for (int q = 0; q < 2; q++) {
        int u = q * NTHR + tid;
        int row = u >> 3, ch = u & 7;
        const __half* ap = g_xh + (size_t)(mBase + row) * DMODEL;
        unsigned off = row * 128 + (((unsigned)(ch ^ (row & 7))) << 4);
        CP_ASYNC16(sbase + off, ap + k0 + ch * 8);
    }
#pragma unroll
    for (int q = 0; q < 4; q++) {
        int u = q * NTHR + tid;
        int row = u >> 3, ch = u & 7;
        const __half* bp = g_w1t + (size_t)(nBase + row) * DMODEL;
        unsigned off = A_BYTES + row * 128 + (((unsigned)(ch ^ (row & 7))) << 4);
        CP_ASYNC16(sbase + off, bp + k0 + ch * 8);
    }
}

__global__ __launch_bounds__(NTHR, 1)
void ffn_tc_kernel(const float* __restrict__ B1, const float* __restrict__ A2) {
    extern __shared__ char dsm[];
    unsigned sbase = smem_u32(dsm);

    int tid = threadIdx.x, wid = tid >> 5, lane = tid & 31;
    int wm = wid & 3, wn = wid >> 2;
    int mBase = blockIdx.y * GBM, nBase = blockIdx.x * GBN;

    float acc[2][8][4] = {};

    issue_stage(sbase + 0 * STAGE_BYTES, 0, mBase, nBase, tid); CP_COMMIT();
    issue_stage(sbase + 1 * STAGE_BYTES, 1, mBase, nBase, tid); CP_COMMIT();

    int grp = lane >> 3, r8 = lane & 7;
    int a_m  = wm * 32 + (grp & 1) * 8 + r8;
    int a_ch = grp >> 1;
    int b_n  = wn * 64 + (grp >> 1) * 8 + r8;
    int b_ch = grp & 1;

    int stageIdx = 0;
    for (int c = 0; c < NCHUNK; c++) {
        if (c >= NCHUNK - 1) { CP_WAIT0(); } else { CP_WAIT1(); }
        __syncthreads();
        if (c + 2 < NCHUNK) {
            int wIdx = stageIdx + 2; if (wIdx >= NSTAGE) wIdx -= NSTAGE;
            issue_stage(sbase + wIdx * STAGE_BYTES, c + 2, mBase, nBase, tid);
            CP_COMMIT();
        }
        unsigned st = sbase + stageIdx * STAGE_BYTES;
#pragma unroll
        for (int ks = 0; ks < 4; ks++) {
            unsigned a[2][4];
#pragma unroll
            for (int mf = 0; mf < 2; mf++) {
                int m = a_m + mf * 16;
                int ch = 2 * ks + a_ch;
                unsigned sw = (((unsigned)(ch ^ (m & 7))) << 4);
                ldmx4(st + m * 128 + sw, a[mf][0], a[mf][1], a[mf][2], a[mf][3]);
            }
            unsigned b[8][2];
#pragma unroll
            for (int nf2 = 0; nf2 < 4; nf2++) {
                int n = b_n + nf2 * 16;
                int ch = 2 * ks + b_ch;
                unsigned addr = st + A_BYTES + n * 128 + (((unsigned)(ch ^ (n & 7))) << 4);
                ldmx4(addr, b[nf2 * 2][0], b[nf2 * 2][1], b[nf2 * 2 + 1][0], b[nf2 * 2 + 1][1]);
            }
#pragma unroll
            for (int mf = 0; mf < 2; mf++)
#pragma unroll
                for (int nf = 0; nf < 8; nf++)
                    mma16816h(acc[mf][nf], a[mf], b[nf]);
        }
        if (++stageIdx == NSTAGE) stageIdx = 0;
    }
    __syncthreads();

    // ---- epilogue ----
    float* ep_w  = (float*)dsm;                       // [256][33]
    float* ep_w2 = (float*)(dsm + 33792);             // [256][2]
    float* ep_g  = (float*)(dsm + 35840);             // [2][128]
    float* ep_u  = (float*)(dsm + 36864);             // [2][128][2]
    int*   ep_e  = (int*)  (dsm + 38912);             // [2][128]

#pragma unroll
    for (int it = 0; it < 16; it++) {
        int idx = it * NTHR + tid;
        int n = idx >> 5, e = (idx >> 2) & 7, q = idx & 3;
        float v;
        if (q < 2) v = B1[(size_t)(e * 2 + q) * FFDIM + nBase + n];
        else       v = A2[(size_t)e * FFDIM * 2 + (size_t)(nBase + n) * 2 + (q - 2)];
        ep_w[n * 33 + e * 4 + q] = v;
    }
    ep_w2[tid] = g_w2wh[nBase * 2 + tid];
    if (tid < 256) {
        int s = tid >> 7, m = tid & 127;
        int t = mBase + m;
        ep_g[s * 128 + m] = g_gate[s][t];
        ep_e[s * 128 + m] = g_exp[s][t];
        ep_u[(s * 128 + m) * 2 + 0] = g_u1[s][t][0];
        ep_u[(s * 128 + m) * 2 + 1] = g_u1[s][t][1];
    }
    __syncthreads();

    const float GC  = 0.7978845608028654f;
    const float T2L = 2.8853900817779268f;
    int quad = lane >> 2, qi = lane & 3;

#pragma unroll
    for (int mf = 0; mf < 2; mf++) {
#pragma unroll
        for (int q8 = 0; q8 < 2; q8++) {
            int m = wm * 32 + mf * 16 + q8 * 8 + quad;
            int t = mBase + m;
#pragma unroll
            for (int s = 0; s < 2; s++) {
                float w = ep_g[s * 128 + m];
                float p0 = 0.f, p1 = 0.f, p2 = 0.f, p3 = 0.f;
                if (w != 0.f) {
                    int e = ep_e[s * 128 + m];
                    float u0 = ep_u[(s * 128 + m) * 2 + 0];
                    float u1 = ep_u[(s * 128 + m) * 2 + 1];
                    const float* wb = ep_w + e * 4;
#pragma unroll
                    for (int nf = 0; nf < 8; nf++) {
#pragma unroll
                        for (int r = 0; r < 2; r++) {
                            int n = wn * 64 + nf * 8 + 2 * qi + r;
                            float av = acc[mf][nf][q8 * 2 + r];
                            float b1r0 = wb[n * 33 + 0], b1r1 = wb[n * 33 + 1];
                            float v = av + u0 * b1r0 + u1 * b1r1;
                            float yy = GC * (v + 0.044715f * v * v * v);
                            float ex = exp2f(yy * T2L);
                            float th = 1.0f - __fdividef(2.0f, ex + 1.0f);
                            float h  = 0.5f * v * (1.0f + th);
                            p0 += h * ep_w2[n * 2];
                            p1 += h * ep_w2[n * 2 + 1];
                            p2 += h * wb[n * 33 + 2];
                            p3 += h * wb[n * 33 + 3];
                        }
                    }
                }
                for (int o = 1; o <= 2; o <<= 1) {
                    p0 += __shfl_xor_sync(~0u, p0, o);
                    p1 += __shfl_xor_sync(~0u, p1, o);
                    p2 += __shfl_xor_sync(~0u, p2, o);
                    p3 += __shfl_xor_sync(~0u, p3, o);
                }
                if (qi == 0 && w != 0.f) {
                    atomicAdd(&g_acc[t][s][0], p0);
                    atomicAdd(&g_acc[t][s][1], p1);
                    atomicAdd(&g_acc[t][s][2], p2);
                    atomicAdd(&g_acc[t][s][3], p3);
                }
            }
        }
    }
}

// ---------------- combine + pool + head output (single kernel, last-block sums) ----
__global__ void final_kernel(const float* __restrict__ bh, float* __restrict__ out) {
    __shared__ float red[256][2];
    int part = blockIdx.x, b = blockIdx.y, tid = threadIdx.x;
    int t = b * SEQ + part * 256 + tid;
    float s0 = 0.f, s1 = 0.f;
#pragma unroll
    for (int s = 0; s < 2; s++) {
        float w = g_gate[s][t];
        if (w != 0.f) {
            int e = g_exp[s][t];
            float d0 = g_acc[t][s][0], d1 = g_acc[t][s][1];
            float a0 = g_acc[t][s][2], a1 = g_acc[t][s][3];
            float z0 = d0 + LSCALE * (a0 * g_b2wh[e * 4 + 0] + a1 * g_b2wh[e * 4 + 2]);
            float z1 = d1 + LSCALE * (a0 * g_b2wh[e * 4 + 1] + a1 * g_b2wh[e * 4 + 3]);
            s0 += w * z0; s1 += w * z1;
        }
    }
    red[tid][0] = s0; red[tid][1] = s1;
    __syncthreads();
    for (int o = 128; o; o >>= 1) {
        if (tid < o) { red[tid][0] += red[tid + o][0]; red[tid][1] += red[tid + o][1]; }
        __syncthreads();
    }
    if (tid == 0) {
        g_part[b][part][0] = red[0][0];
        g_part[b][part][1] = red[0][1];
        __threadfence();
        unsigned done = atomicAdd(&g_done, 1);
        if (done == NBATCH * 8 - 1) {              // last block: fold partials
            g_done = 0;                            // reset for next graph replay
#pragma unroll
            for (int bb = 0; bb < NBATCH; bb++) {
                float t0 = 0.f, t1 = 0.f;
#pragma unroll
                for (int p = 0; p < 8; p++) { t0 += g_part[bb][p][0]; t1 += g_part[bb][p][1]; }
                out[bb * 2 + 0] = t0 / (float)SEQ + bh[0];
                out[bb * 2 + 1] = t1 / (float)SEQ + bh[1];
            }
        }
    }
}

// ---------------- launch ----------------
extern "C" void kernel_launch(void* const* d_in, const int* in_sizes, int n_in,
                              void* d_out, int out_size) {
    const float* x  = (const float*)d_in[0];
    const float* Wg = (const float*)d_in[1];
    const float* W1 = (const float*)d_in[2];
    const float* W2 = (const float*)d_in[3];
    const float* A1 = (const float*)d_in[4];
    const float* B1 = (const float*)d_in[5];
    const float* A2 = (const float*)d_in[6];
    const float* B2 = (const float*)d_in[7];
    const float* Wh = (const float*)d_in[8];
    const float* bh = (const float*)d_in[9];

    cudaFuncSetAttribute(ffn_tc_kernel, cudaFuncAttributeMaxDynamicSharedMemorySize, SMEM_REQ);

    aux_kernel<<<GATE_BLOCKS + CONVW_BLOCKS + PREP_BLOCKS, 256>>>(x, Wg, A1, W1, W2, Wh, B2);
    route_kernel<<<1, 1024>>>();
    ffn_tc_kernel<<<dim3(FFDIM / GBN, T_TOK / GBM), NTHR, SMEM_REQ>>>(B1, A2);
    final_kernel<<<dim3(8, NBATCH), 256>>>(bh, (float*)d_out);
}